// round 7
// baseline (speedup 1.0000x reference)
#include <cuda_runtime.h>
#include <cuda_bf16.h>
#include <math.h>
#include <stdint.h>

// Problem dims (fixed)
#define B   64
#define S   128
#define H   256
#define H2  512
#define H3  768
#define H4  1024
#define V   32000
#define T   32
#define NVT 250        // vocab tiles = V/128

#define KSPLIT_G 8     // gates GEMM k-split

// ------------------------- scratch (static device globals) -------------------------
__device__ float g_encp[B * S * H2];          // enc @ Ww.T + Wb   (16.8 MB)
__device__ float g_UwS[H2 * H];               // Uw[:, :H] + Uw[:, H:]
__device__ float g_ctx[B * H2];               // attention context
__device__ float g_Wcat[2 * H4 * H4];         // [Wih | Whh] per direction (8 MB)
__device__ float g_bcat[2 * H4];
__device__ float g_Gp[KSPLIT_G * 2 * B * H4]; // split-K partial gate sums (4 MB)
__device__ float g_h[2 * B * H];
__device__ float g_c[2 * B * H];
__device__ int   g_x[B];                      // greedy token feedback
__device__ float g_pval[NVT * B];             // per-tile argmax partials
__device__ int   g_pidx[NVT * B];
// bf16x3 split operands for the vocab GEMM
__device__ __nv_bfloat16 g_Fw_hi[(size_t)V * H2];   // 32.8 MB
__device__ __nv_bfloat16 g_Fw_lo[(size_t)V * H2];   // 32.8 MB
__device__ __nv_bfloat16 g_out_hi[B * H2];
__device__ __nv_bfloat16 g_out_lo[B * H2];

__device__ __forceinline__ float warpsum(float v) {
    #pragma unroll
    for (int o = 16; o > 0; o >>= 1) v += __shfl_xor_sync(0xffffffffu, v, o);
    return v;
}
__device__ __forceinline__ float warpmax(float v) {
    #pragma unroll
    for (int o = 16; o > 0; o >>= 1) v = fmaxf(v, __shfl_xor_sync(0xffffffffu, v, o));
    return v;
}
__device__ __forceinline__ float sigf(float x) { return 1.0f / (1.0f + expf(-x)); }

// ------------------------- portable PTX helpers (sm_80+ baseline) -------------------
__device__ __forceinline__ uint32_t smem_u32(const void* p) {
    uint32_t a;
    asm("{ .reg .u64 t; cvta.to.shared.u64 t, %1; cvt.u32.u64 %0, t; }" : "=r"(a) : "l"(p));
    return a;
}
#define SWZ(x) ((x) ^ (((x) >> 3) & 0x70))

#define CP16(saddr, gptr) \
    asm volatile("cp.async.cg.shared.global [%0], [%1], 16;" :: "r"(saddr), "l"(gptr))
#define CP_COMMIT() asm volatile("cp.async.commit_group;" ::: "memory")
#define CP_WAIT(n)  asm volatile("cp.async.wait_group %0;" :: "n"(n) : "memory")

__device__ __forceinline__ void ldsm4(uint32_t* r, uint32_t addr) {
    asm volatile("ldmatrix.sync.aligned.m8n8.x4.shared.b16 {%0,%1,%2,%3}, [%4];"
        : "=r"(r[0]), "=r"(r[1]), "=r"(r[2]), "=r"(r[3]) : "r"(addr));
}
__device__ __forceinline__ void mma16816(float* c, const uint32_t* a, const uint32_t* b) {
    asm volatile("mma.sync.aligned.m16n8k16.row.col.f32.bf16.bf16.f32 "
        "{%0,%1,%2,%3}, {%4,%5,%6,%7}, {%8,%9}, {%0,%1,%2,%3};"
        : "+f"(c[0]), "+f"(c[1]), "+f"(c[2]), "+f"(c[3])
        : "r"(a[0]), "r"(a[1]), "r"(a[2]), "r"(a[3]), "r"(b[0]), "r"(b[1]));
}

// ------------------------- one-time pack / init -------------------------
__global__ void pack_kernel(const float* __restrict__ Uw,
                            const float* __restrict__ Wih_f, const float* __restrict__ Whh_f,
                            const float* __restrict__ b_f,
                            const float* __restrict__ Wih_b, const float* __restrict__ Whh_b,
                            const float* __restrict__ b_b,
                            const float* __restrict__ h0, const float* __restrict__ c0) {
    const size_t NTOT = (size_t)2 * H4 * H4;  // 2,097,152
    for (size_t idx = (size_t)blockIdx.x * blockDim.x + threadIdx.x; idx < NTOT;
         idx += (size_t)gridDim.x * blockDim.x) {
        size_t d = idx >> 20;
        size_t r = (idx >> 10) & 1023;
        size_t k = idx & 1023;
        const float* Wih = d ? Wih_b : Wih_f;
        const float* Whh = d ? Whh_b : Whh_f;
        g_Wcat[idx] = (k < H3) ? Wih[r * H3 + k] : Whh[r * H + (k - H3)];

        if (idx < (size_t)H2 * H) {
            size_t j = idx >> 8, kk = idx & 255;
            g_UwS[idx] = Uw[j * H2 + kk] + Uw[j * H2 + H + kk];
        }
        if (idx < 2 * H4) g_bcat[idx] = (idx < H4) ? b_f[idx] : b_b[idx - H4];
        if (idx < 2 * B * H) { g_h[idx] = h0[idx]; g_c[idx] = c0[idx]; }
        if (idx < B) g_x[idx] = 0;
    }
}

// split Fw into hi/lo bf16 once
__global__ void pack_fw_kernel(const float* __restrict__ Fw) {
    const size_t NTOT = (size_t)V * H2;
    for (size_t i = (size_t)blockIdx.x * blockDim.x + threadIdx.x; i < NTOT;
         i += (size_t)gridDim.x * blockDim.x) {
        float v = Fw[i];
        __nv_bfloat16 hi = __float2bfloat16(v);
        g_Fw_hi[i] = hi;
        g_Fw_lo[i] = __float2bfloat16(v - __bfloat162float(hi));
    }
}

// ------------------------- double-buffered fp32 GEMM (encoder projection) -----------
#define GBM 64
#define GBN 128
#define GBK 32
__global__ void __launch_bounds__(256) gemm_abt(
    const float* __restrict__ A, const float* __restrict__ W,
    const float* __restrict__ bias, float* __restrict__ C,
    int M, int N, int K, int ldC) {
    __shared__ float As[2][GBK][GBM];
    __shared__ float Bs[2][GBK][GBN];

    const int tid = threadIdx.x;
    const int tx = tid & 15, ty = tid >> 4;
    const int mBase = blockIdx.y * GBM;
    const int nBase = blockIdx.x * GBN;

    const int ar0 = (tid) >> 3,        akq0 = tid & 7;
    const int ar1 = (tid + 256) >> 3,  akq1 = tid & 7;
    float acc[4][8];
    #pragma unroll
    for (int i = 0; i < 4; i++)
        #pragma unroll
        for (int j = 0; j < 8; j++) acc[i][j] = 0.0f;

    float4 ra[2], rb[4];

    #define LOAD_TILE(k0)                                                                 \
        do {                                                                              \
            ra[0] = *reinterpret_cast<const float4*>(&A[(size_t)(mBase + ar0) * K + (k0) + akq0 * 4]); \
            ra[1] = *reinterpret_cast<const float4*>(&A[(size_t)(mBase + ar1) * K + (k0) + akq1 * 4]); \
            _Pragma("unroll")                                                             \
            for (int i = 0; i < 4; i++) {                                                 \
                int f4 = tid + 256 * i; int r = f4 >> 3, kq = f4 & 7;                     \
                rb[i] = *reinterpret_cast<const float4*>(&W[(size_t)(nBase + r) * K + (k0) + kq * 4]); \
            }                                                                             \
        } while (0)

    #define STORE_TILE(bi)                                                                \
        do {                                                                              \
            As[bi][akq0 * 4 + 0][ar0] = ra[0].x; As[bi][akq0 * 4 + 1][ar0] = ra[0].y;     \
            As[bi][akq0 * 4 + 2][ar0] = ra[0].z; As[bi][akq0 * 4 + 3][ar0] = ra[0].w;     \
            As[bi][akq1 * 4 + 0][ar1] = ra[1].x; As[bi][akq1 * 4 + 1][ar1] = ra[1].y;     \
            As[bi][akq1 * 4 + 2][ar1] = ra[1].z; As[bi][akq1 * 4 + 3][ar1] = ra[1].w;     \
            _Pragma("unroll")                                                             \
            for (int i = 0; i < 4; i++) {                                                 \
                int f4 = tid + 256 * i; int r = f4 >> 3, kq = f4 & 7;                     \
                Bs[bi][kq * 4 + 0][r] = rb[i].x; Bs[bi][kq * 4 + 1][r] = rb[i].y;         \
                Bs[bi][kq * 4 + 2][r] = rb[i].z; Bs[bi][kq * 4 + 3][r] = rb[i].w;         \
            }                                                                             \
        } while (0)

    #define COMPUTE(bi)                                                                   \
        do {                                                                              \
            _Pragma("unroll")                                                             \
            for (int k = 0; k < GBK; k++) {                                               \
                float4 a4 = *reinterpret_cast<const float4*>(&As[bi][k][ty * 4]);         \
                float4 b0 = *reinterpret_cast<const float4*>(&Bs[bi][k][tx * 8]);         \
                float4 b1 = *reinterpret_cast<const float4*>(&Bs[bi][k][tx * 8 + 4]);     \
                float a[4] = {a4.x, a4.y, a4.z, a4.w};                                    \
                float b[8] = {b0.x, b0.y, b0.z, b0.w, b1.x, b1.y, b1.z, b1.w};            \
                _Pragma("unroll")                                                         \
                for (int i = 0; i < 4; i++)                                               \
                    _Pragma("unroll")                                                     \
                    for (int j = 0; j < 8; j++) acc[i][j] = fmaf(a[i], b[j], acc[i][j]);  \
            }                                                                             \
        } while (0)

    const int nIter = K / GBK;
    LOAD_TILE(0);
    STORE_TILE(0);
    __syncthreads();
    int buf = 0;
    for (int it = 1; it < nIter; it++) {
        LOAD_TILE(it * GBK);
        COMPUTE(buf);
        STORE_TILE(buf ^ 1);
        __syncthreads();
        buf ^= 1;
    }
    COMPUTE(buf);

    #pragma unroll
    for (int i = 0; i < 4; i++) {
        size_t row = (size_t)(mBase + ty * 4 + i);
        #pragma unroll
        for (int j = 0; j < 8; j++) {
            int col = nBase + tx * 8 + j;
            C[row * (size_t)ldC + col] = acc[i][j] + bias[col];
        }
    }
}

// ------------------------- gates GEMM with fused [ctx|emb|h] gather -----------------
// G_partial[d][b][n] over k-slice ks. grid (H4/GBN=8, KSPLIT_G, 2), 256 thr.
// k-slices of 128 fall entirely inside one source region (512/768 are multiples of 128).
__global__ void __launch_bounds__(256) gates_gemm(const float* __restrict__ embt) {
    const int dz = blockIdx.z;
    const int ks = blockIdx.y;
    const int kBegin = ks * (H4 / KSPLIT_G);           // 128-wide slice
    const float* __restrict__ W = g_Wcat + (size_t)dz * H4 * H4;
    float* __restrict__ C = g_Gp + (size_t)ks * 2 * B * H4 + (size_t)dz * B * H4;

    __shared__ float As[2][GBK][GBM];
    __shared__ float Bs[2][GBK][GBN];

    const int tid = threadIdx.x;
    const int tx = tid & 15, ty = tid >> 4;
    const int nBase = blockIdx.x * GBN;

    const int ar0 = (tid) >> 3,        akq0 = tid & 7;
    const int ar1 = (tid + 256) >> 3,  akq1 = tid & 7;

    // region-resolved A row pointers (row = batch)
    const float* aptr0;
    const float* aptr1;
    if (kBegin < H2) {
        aptr0 = g_ctx + (size_t)ar0 * H2 + kBegin;
        aptr1 = g_ctx + (size_t)ar1 * H2 + kBegin;
    } else if (kBegin < H3) {
        aptr0 = embt + (size_t)g_x[ar0] * H + (kBegin - H2);
        aptr1 = embt + (size_t)g_x[ar1] * H + (kBegin - H2);
    } else {
        aptr0 = g_h + ((size_t)dz * B + ar0) * H + (kBegin - H3);
        aptr1 = g_h + ((size_t)dz * B + ar1) * H + (kBegin - H3);
    }

    float acc[4][8];
    #pragma unroll
    for (int i = 0; i < 4; i++)
        #pragma unroll
        for (int j = 0; j < 8; j++) acc[i][j] = 0.0f;

    float4 ra[2], rb[4];

    #define GLOAD_TILE(koff)                                                              \
        do {                                                                              \
            ra[0] = *reinterpret_cast<const float4*>(aptr0 + (koff) + akq0 * 4);          \
            ra[1] = *reinterpret_cast<const float4*>(aptr1 + (koff) + akq1 * 4);          \
            _Pragma("unroll")                                                             \
            for (int i = 0; i < 4; i++) {                                                 \
                int f4 = tid + 256 * i; int r = f4 >> 3, kq = f4 & 7;                     \
                rb[i] = *reinterpret_cast<const float4*>(&W[(size_t)(nBase + r) * H4 + kBegin + (koff) + kq * 4]); \
            }                                                                             \
        } while (0)

    const int nIter = (H4 / KSPLIT_G) / GBK;   // 4
    GLOAD_TILE(0);
    STORE_TILE(0);
    __syncthreads();
    int buf = 0;
    for (int it = 1; it < nIter; it++) {
        GLOAD_TILE(it * GBK);
        COMPUTE(buf);
        STORE_TILE(buf ^ 1);
        __syncthreads();
        buf ^= 1;
    }
    COMPUTE(buf);

    #pragma unroll
    for (int i = 0; i < 4; i++) {
        size_t row = (size_t)(ty * 4 + i);
        #pragma unroll
        for (int j = 0; j < 8; j++) {
            int col = nBase + tx * 8 + j;
            float bj = (ks == 0) ? g_bcat[dz * H4 + col] : 0.0f;
            C[row * H4 + col] = acc[i][j] + bj;
        }
    }
    #undef GLOAD_TILE
    #undef LOAD_TILE
    #undef STORE_TILE
    #undef COMPUTE
}

// ------------------------- fused attention: qU + score + softmax + ctx --------------
// grid = B, 512 threads (16 warps)
__global__ void __launch_bounds__(512) attn_fused(const float* __restrict__ enc,
                                                  const float* __restrict__ Ub,
                                                  const float* __restrict__ Vw,
                                                  const float* __restrict__ Vb) {
    __shared__ float h_s[H];
    __shared__ float qU[H2];
    __shared__ float vs[H2];
    __shared__ float sc[S];
    __shared__ float red[8];
    const int b = blockIdx.x, tid = threadIdx.x;
    const int warp = tid >> 5, lane = tid & 31;

    if (tid < H) h_s[tid] = g_h[(size_t)b * H + tid];
    vs[tid] = Vw[tid];
    __syncthreads();

    // qU[j] = Ub[j] + dot(UwS[j,:], h_s)   — 16 warps x 32 j, 2 j's in flight
    #pragma unroll 2
    for (int jj = 0; jj < 32; jj += 2) {
        int j0 = warp * 32 + jj;
        const float* u0 = g_UwS + (size_t)j0 * H;
        const float* u1 = u0 + H;
        float4 a0 = *reinterpret_cast<const float4*>(u0 + lane * 4);
        float4 a1 = *reinterpret_cast<const float4*>(u0 + 128 + lane * 4);
        float4 b0 = *reinterpret_cast<const float4*>(u1 + lane * 4);
        float4 b1 = *reinterpret_cast<const float4*>(u1 + 128 + lane * 4);
        float4 h0 = *reinterpret_cast<const float4*>(h_s + lane * 4);
        float4 h1 = *reinterpret_cast<const float4*>(h_s + 128 + lane * 4);
        float s0 = a0.x * h0.x + a0.y * h0.y + a0.z * h0.z + a0.w * h0.w
                 + a1.x * h1.x + a1.y * h1.y + a1.z * h1.z + a1.w * h1.w;
        float s1 = b0.x * h0.x + b0.y * h0.y + b0.z * h0.z + b0.w * h0.w
                 + b1.x * h1.x + b1.y * h1.y + b1.z * h1.z + b1.w * h1.w;
        s0 = warpsum(s0);
        s1 = warpsum(s1);
        if (lane == 0) { qU[j0] = s0 + Ub[j0]; qU[j0 + 1] = s1 + Ub[j0 + 1]; }
    }
    __syncthreads();

    // scores: 16 warps x 8 s
    float vb = Vb[0];
    #pragma unroll
    for (int ss = 0; ss < 8; ss++) {
        int s = warp * 8 + ss;
        const float* ep = g_encp + ((size_t)b * S + s) * H2;
        float acc = 0.0f;
        #pragma unroll
        for (int it = 0; it < 4; it++) {
            int k = it * 128 + lane * 4;
            float4 e4 = *reinterpret_cast<const float4*>(ep + k);
            float4 q4 = *reinterpret_cast<const float4*>(qU + k);
            float4 v4 = *reinterpret_cast<const float4*>(vs + k);
            acc += v4.x * tanhf(q4.x + e4.x) + v4.y * tanhf(q4.y + e4.y)
                 + v4.z * tanhf(q4.z + e4.z) + v4.w * tanhf(q4.w + e4.w);
        }
        acc = warpsum(acc);
        if (lane == 0) sc[s] = acc + vb;
    }
    __syncthreads();

    // softmax over S=128 (threads 0..127)
    if (tid < S) {
        float x = sc[tid];
        float m = warpmax(x);
        if (lane == 0) red[warp] = m;
    }
    __syncthreads();
    if (tid < S) {
        float mx = fmaxf(fmaxf(red[0], red[1]), fmaxf(red[2], red[3]));
        float e = expf(sc[tid] - mx);
        sc[tid] = e;
        float su = warpsum(e);
        if (lane == 0) red[4 + warp] = su;
    }
    __syncthreads();
    float inv = 1.0f / (red[4] + red[5] + red[6] + red[7]);
    // ctx: d = tid, 512 threads
    {
        const float* eb = enc + (size_t)b * S * H2 + tid;
        float acc = 0.0f;
        #pragma unroll 8
        for (int s = 0; s < S; s++) acc += sc[s] * eb[(size_t)s * H2];
        g_ctx[(size_t)b * H2 + tid] = acc * inv;
    }
}

// ------------------------- LSTM activation (+ hi/lo split of out) -------------------
__global__ void lstm_act_kernel() {
    int idx = blockIdx.x * blockDim.x + threadIdx.x;
    if (idx >= 2 * B * H) return;
    int d = idx / (B * H);
    int b = (idx / H) % B;
    int k = idx % H;
    size_t base = ((size_t)d * B + b) * H4;
    float gi = 0, gf = 0, gg = 0, go = 0;
    #pragma unroll
    for (int s = 0; s < KSPLIT_G; s++) {
        const float* Gp = g_Gp + (size_t)s * 2 * B * H4 + base;
        gi += Gp[k]; gf += Gp[H + k]; gg += Gp[2 * H + k]; go += Gp[3 * H + k];
    }
    float c_old = g_c[idx];
    float c2 = sigf(gf) * c_old + sigf(gi) * tanhf(gg);
    float h2 = sigf(go) * tanhf(c2);
    g_c[idx] = c2;
    g_h[idx] = h2;
    int o = b * H2 + d * H + k;
    __nv_bfloat16 hi = __float2bfloat16(h2);
    g_out_hi[o] = hi;
    g_out_lo[o] = __float2bfloat16(h2 - __bfloat162float(hi));
}

// ------------------------- vocab GEMM: mma.sync bf16x3 + fused partial argmax -------
#define VSM_DYN (98304 + 1024)

__device__ __forceinline__ void vissue_chunk(uint32_t tb, int v0, int c, int buf, int tid) {
    const uint32_t AHI = tb + buf * 16384u, ALO = tb + 32768u + buf * 16384u;
    const uint32_t BHI = tb + 65536u + buf * 8192u, BLO = tb + 81920u + buf * 8192u;
    #pragma unroll
    for (int i = 0; i < 4; i++) {
        int idx = tid + 256 * i;
        int r = idx >> 3, q = idx & 7;
        size_t g = (size_t)(v0 + r) * H2 + c * 64 + q * 8;
        uint32_t so = SWZ((uint32_t)(r * 128 + q * 16));
        CP16(AHI + so, (const char*)(g_Fw_hi + g));
        CP16(ALO + so, (const char*)(g_Fw_lo + g));
    }
    #pragma unroll
    for (int i = 0; i < 2; i++) {
        int idx = tid + 256 * i;
        int r = idx >> 3, q = idx & 7;
        size_t g = (size_t)r * H2 + c * 64 + q * 8;
        uint32_t so = SWZ((uint32_t)(r * 128 + q * 16));
        CP16(BHI + so, (const char*)(g_out_hi + g));
        CP16(BLO + so, (const char*)(g_out_lo + g));
    }
    CP_COMMIT();
}

__global__ void __launch_bounds__(256, 2) vocab_kernel(const float* __restrict__ Fb,
                                                       float* __restrict__ yt) {
    extern __shared__ char dsm[];
    uint32_t sb0 = smem_u32(dsm);
    uint32_t tb = (sb0 + 1023) & ~1023u;
    char* base = dsm + (tb - sb0);

    const int tid = threadIdx.x;
    const int wid = tid >> 5, lane = tid & 31;
    const int v0 = blockIdx.x * 128;
    const int wm = wid * 16;

    const int a_row = wm + (lane & 7) + ((lane >> 3) & 1) * 8;
    const int a_kb  = (lane >> 4) * 16;
    const int b_rowi = (lane & 7) + (lane >> 4) * 8;
    const int b_kb  = ((lane >> 3) & 1) * 16;

    float acc[8][4];
    #pragma unroll
    for (int i = 0; i < 8; i++)
        #pragma unroll
        for (int j = 0; j < 4; j++) acc[i][j] = 0.0f;

    vissue_chunk(tb, v0, 0, 0, tid);
    vissue_chunk(tb, v0, 1, 1, tid);

    for (int c = 0; c < 8; c++) {
        const int buf = c & 1;
        if (c < 7) { CP_WAIT(1); } else { CP_WAIT(0); }
        __syncthreads();

        const uint32_t AHI = tb + buf * 16384u, ALO = tb + 32768u + buf * 16384u;
        const uint32_t BHI = tb + 65536u + buf * 8192u, BLO = tb + 81920u + buf * 8192u;

        #pragma unroll
        for (int ks = 0; ks < 4; ks++) {
            uint32_t ah[4], al[4];
            uint32_t aoff = SWZ((uint32_t)(a_row * 128 + ks * 32 + a_kb));
            ldsm4(ah, AHI + aoff);
            ldsm4(al, ALO + aoff);
            #pragma unroll
            for (int p = 0; p < 4; p++) {
                uint32_t bh[4], bl[4];
                uint32_t boff = SWZ((uint32_t)((b_rowi + p * 16) * 128 + ks * 32 + b_kb));
                ldsm4(bh, BHI + boff);
                ldsm4(bl, BLO + boff);
                mma16816(acc[2 * p],     ah, bh);
                mma16816(acc[2 * p],     al, bh);
                mma16816(acc[2 * p],     ah, bl);
                mma16816(acc[2 * p + 1], ah, bh + 2);
                mma16816(acc[2 * p + 1], al, bh + 2);
                mma16816(acc[2 * p + 1], ah, bl + 2);
            }
        }
        __syncthreads();
        if (c < 6) vissue_chunk(tb, v0, c + 2, buf, tid);
    }

    // epilogue: transpose via smem
    float* tr = (float*)base;   // [64 batch][132]
    {
        const int m0 = wm + (lane >> 2);
        const int nb = 2 * (lane & 3);
        #pragma unroll
        for (int nt = 0; nt < 8; nt++) {
            int n = nt * 8 + nb;
            tr[n * 132 + m0]           = acc[nt][0];
            tr[(n + 1) * 132 + m0]     = acc[nt][1];
            tr[n * 132 + m0 + 8]       = acc[nt][2];
            tr[(n + 1) * 132 + m0 + 8] = acc[nt][3];
        }
    }
    __syncthreads();

    // store with bias + per-(tile,b) argmax partial (first-index tie-break)
    float* pm = tr + 64 * 132;
    int*   pi = (int*)(pm + 256);
    {
        const int bb = tid >> 2;      // batch
        const int t4 = tid & 3;
        float bestv = -INFINITY; int besti = 0x7fffffff;
        #pragma unroll
        for (int i = 0; i < 8; i++) {
            int j = t4 * 8 + i;       // float4 index, ascending v within thread
            float4 fb4 = *reinterpret_cast<const float4*>(&Fb[v0 + 4 * j]);
            float4 t = *reinterpret_cast<const float4*>(&tr[bb * 132 + 4 * j]);
            float4 r;
            r.x = t.x + fb4.x; r.y = t.y + fb4.y; r.z = t.z + fb4.z; r.w = t.w + fb4.w;
            *reinterpret_cast<float4*>(&yt[(size_t)bb * T * V + v0 + 4 * j]) = r;
            int vbase = v0 + 4 * j;
            if (r.x > bestv) { bestv = r.x; besti = vbase; }
            if (r.y > bestv) { bestv = r.y; besti = vbase + 1; }
            if (r.z > bestv) { bestv = r.z; besti = vbase + 2; }
            if (r.w > bestv) { bestv = r.w; besti = vbase + 3; }
        }
        pm[tid] = bestv; pi[tid] = besti;
    }
    __syncthreads();
    if ((tid & 3) == 0) {
        float bv = pm[tid]; int bi = pi[tid];
        #pragma unroll
        for (int t = 1; t < 4; t++) {        // ascending t4 = ascending v
            float v2 = pm[tid + t];
            if (v2 > bv) { bv = v2; bi = pi[tid + t]; }
        }
        int bb = tid >> 2;
        g_pval[blockIdx.x * B + bb] = bv;
        g_pidx[blockIdx.x * B + bb] = bi;
    }
}

// ------------------------- argmax final reduce over 250 tile partials ---------------
__global__ void __launch_bounds__(256) argmax_final() {
    int b = blockIdx.x, tid = threadIdx.x;
    float v = -INFINITY; int ix = 0x7fffffff;
    if (tid < NVT) { v = g_pval[tid * B + b]; ix = g_pidx[tid * B + b]; }
    __shared__ float bv[256];
    __shared__ int   bx[256];
    bv[tid] = v; bx[tid] = ix;
    __syncthreads();
    for (int st = 128; st > 0; st >>= 1) {
        if (tid < st) {
            if (bv[tid + st] > bv[tid] ||
                (bv[tid + st] == bv[tid] && bx[tid + st] < bx[tid])) {
                bv[tid] = bv[tid + st]; bx[tid] = bx[tid + st];
            }
        }
        __syncthreads();
    }
    if (tid == 0) g_x[b] = bx[0];
}

// ------------------------- tail: hT, cT -------------------------
__global__ void tail_kernel(float* __restrict__ out) {
    int idx = blockIdx.x * blockDim.x + threadIdx.x;
    if (idx < 2 * B * H) {
        out[(size_t)B * T * V + idx] = g_h[idx];
        out[(size_t)B * T * V + 2 * B * H + idx] = g_c[idx];
    }
}

// ------------------------- host -------------------------
extern "C" void kernel_launch(void* const* d_in, const int* in_sizes, int n_in,
                              void* d_out, int out_size) {
    const float* enc   = (const float*)d_in[0];
    const float* h0    = (const float*)d_in[1];
    const float* c0    = (const float*)d_in[2];
    const float* Uw    = (const float*)d_in[3];
    const float* Ub    = (const float*)d_in[4];
    const float* Ww    = (const float*)d_in[5];
    const float* Wb    = (const float*)d_in[6];
    const float* Vw    = (const float*)d_in[7];
    const float* Vb    = (const float*)d_in[8];
    const float* Wih_f = (const float*)d_in[9];
    const float* Whh_f = (const float*)d_in[10];
    const float* b_f   = (const float*)d_in[11];
    const float* Wih_b = (const float*)d_in[12];
    const float* Whh_b = (const float*)d_in[13];
    const float* b_b   = (const float*)d_in[14];
    const float* Fw    = (const float*)d_in[15];
    const float* Fb    = (const float*)d_in[16];
    const float* embt  = (const float*)d_in[17];
    (void)in_sizes; (void)n_in;
    float* out = (float*)d_out;

    static bool attr_set = false;
    if (!attr_set) {
        cudaFuncSetAttribute(vocab_kernel, cudaFuncAttributeMaxDynamicSharedMemorySize, VSM_DYN);
        attr_set = true;
    }

    // one-time packing + state init
    pack_kernel<<<2048, 1024>>>(Uw, Wih_f, Whh_f, b_f, Wih_b, Whh_b, b_b, h0, c0);
    pack_fw_kernel<<<4096, 256>>>(Fw);

    // enc_proj = enc @ Ww.T + Wb
    {
        float* encp;  cudaGetSymbolAddress((void**)&encp, g_encp);
        gemm_abt<<<dim3(H2 / GBN, (B * S) / GBM, 1), 256>>>(
            enc, Ww, Wb, encp, B * S, H2, H2, H2);
    }

    for (int t = 0; t < T; t++) {
        attn_fused<<<B, 512>>>(enc, Ub, Vw, Vb);
        gates_gemm<<<dim3(H4 / GBN, KSPLIT_G, 2), 256>>>(embt);
        lstm_act_kernel<<<(2 * B * H) / 256, 256>>>();
        vocab_kernel<<<NVT, 256, VSM_DYN>>>(Fb, out + (size_t)t * V);
        argmax_final<<<B, 256>>>();
    }

    if (out_size >= B * T * V + 4 * B * H)
        tail_kernel<<<(2 * B * H + 255) / 256, 256>>>(out);
}

// round 8
// speedup vs baseline: 1.0324x; 1.0324x over previous
#include <cuda_runtime.h>
#include <cuda_bf16.h>
#include <math.h>
#include <stdint.h>

// Problem dims (fixed)
#define B   64
#define S   128
#define H   256
#define H2  512
#define H3  768
#define H4  1024
#define V   32000
#define T   32
#define NVT 250        // vocab tiles = V/128

#define KSPLIT_G 8     // gates GEMM k-split

// ------------------------- scratch (static device globals) -------------------------
__device__ float g_encp[B * S * H2];          // enc @ Ww.T + Wb   (16.8 MB)
__device__ float g_UwS[H2 * H];               // Uw[:, :H] + Uw[:, H:]
__device__ float g_qU[B * H2];                // h_f @ UwS.T + Ub
__device__ float g_score[B * S];              // raw attention scores
__device__ float g_ctx[B * H2];               // attention context
__device__ float g_Wcat[2 * H4 * H4];         // [Wih | Whh] per direction (8 MB)
__device__ float g_bcat[2 * H4];
__device__ float g_Gp[KSPLIT_G * 2 * B * H4]; // split-K partial gate sums (4 MB)
__device__ float g_h[2 * B * H];
__device__ float g_c[2 * B * H];
__device__ float g_pval[B * NVT];             // per-(batch,tile) argmax partials
__device__ int   g_pidx[B * NVT];
// bf16x3 split operands for the vocab GEMM
__device__ __nv_bfloat16 g_Fw_hi[(size_t)V * H2];   // 32.8 MB
__device__ __nv_bfloat16 g_Fw_lo[(size_t)V * H2];   // 32.8 MB
__device__ __nv_bfloat16 g_out_hi[B * H2];
__device__ __nv_bfloat16 g_out_lo[B * H2];

__device__ __forceinline__ float warpsum(float v) {
    #pragma unroll
    for (int o = 16; o > 0; o >>= 1) v += __shfl_xor_sync(0xffffffffu, v, o);
    return v;
}
__device__ __forceinline__ float warpmax(float v) {
    #pragma unroll
    for (int o = 16; o > 0; o >>= 1) v = fmaxf(v, __shfl_xor_sync(0xffffffffu, v, o));
    return v;
}
__device__ __forceinline__ float sigf(float x) { return 1.0f / (1.0f + expf(-x)); }

// ------------------------- portable PTX helpers (sm_80+ baseline) -------------------
__device__ __forceinline__ uint32_t smem_u32(const void* p) {
    uint32_t a;
    asm("{ .reg .u64 t; cvta.to.shared.u64 t, %1; cvt.u32.u64 %0, t; }" : "=r"(a) : "l"(p));
    return a;
}
#define SWZ(x) ((x) ^ (((x) >> 3) & 0x70))

#define CP16(saddr, gptr) \
    asm volatile("cp.async.cg.shared.global [%0], [%1], 16;" :: "r"(saddr), "l"(gptr))
#define CP_COMMIT() asm volatile("cp.async.commit_group;" ::: "memory")
#define CP_WAIT(n)  asm volatile("cp.async.wait_group %0;" :: "n"(n) : "memory")

__device__ __forceinline__ void ldsm4(uint32_t* r, uint32_t addr) {
    asm volatile("ldmatrix.sync.aligned.m8n8.x4.shared.b16 {%0,%1,%2,%3}, [%4];"
        : "=r"(r[0]), "=r"(r[1]), "=r"(r[2]), "=r"(r[3]) : "r"(addr));
}
__device__ __forceinline__ void mma16816(float* c, const uint32_t* a, const uint32_t* b) {
    asm volatile("mma.sync.aligned.m16n8k16.row.col.f32.bf16.bf16.f32 "
        "{%0,%1,%2,%3}, {%4,%5,%6,%7}, {%8,%9}, {%0,%1,%2,%3};"
        : "+f"(c[0]), "+f"(c[1]), "+f"(c[2]), "+f"(c[3])
        : "r"(a[0]), "r"(a[1]), "r"(a[2]), "r"(a[3]), "r"(b[0]), "r"(b[1]));
}

// ------------------------- one-time pack / init -------------------------
__global__ void pack_kernel(const float* __restrict__ Uw,
                            const float* __restrict__ Wih_f, const float* __restrict__ Whh_f,
                            const float* __restrict__ b_f,
                            const float* __restrict__ Wih_b, const float* __restrict__ Whh_b,
                            const float* __restrict__ b_b,
                            const float* __restrict__ h0, const float* __restrict__ c0) {
    const size_t NTOT = (size_t)2 * H4 * H4;  // 2,097,152
    for (size_t idx = (size_t)blockIdx.x * blockDim.x + threadIdx.x; idx < NTOT;
         idx += (size_t)gridDim.x * blockDim.x) {
        size_t d = idx >> 20;
        size_t r = (idx >> 10) & 1023;
        size_t k = idx & 1023;
        const float* Wih = d ? Wih_b : Wih_f;
        const float* Whh = d ? Whh_b : Whh_f;
        g_Wcat[idx] = (k < H3) ? Wih[r * H3 + k] : Whh[r * H + (k - H3)];

        if (idx < (size_t)H2 * H) {
            size_t j = idx >> 8, kk = idx & 255;
            g_UwS[idx] = Uw[j * H2 + kk] + Uw[j * H2 + H + kk];
        }
        if (idx < 2 * H4) g_bcat[idx] = (idx < H4) ? b_f[idx] : b_b[idx - H4];
        if (idx < 2 * B * H) { g_h[idx] = h0[idx]; g_c[idx] = c0[idx]; }
        // argmax partials: step 0 must resolve to token 0 (x0 = zeros)
        if (idx < (size_t)B * NVT) {
            int tl = (int)(idx % NVT);
            g_pval[idx] = (tl == 0) ? 0.0f : -INFINITY;
            g_pidx[idx] = (tl == 0) ? 0 : 0x7fffffff;
        }
    }
}

// split Fw into hi/lo bf16 once
__global__ void pack_fw_kernel(const float* __restrict__ Fw) {
    const size_t NTOT = (size_t)V * H2;
    for (size_t i = (size_t)blockIdx.x * blockDim.x + threadIdx.x; i < NTOT;
         i += (size_t)gridDim.x * blockDim.x) {
        float v = Fw[i];
        __nv_bfloat16 hi = __float2bfloat16(v);
        g_Fw_hi[i] = hi;
        g_Fw_lo[i] = __float2bfloat16(v - __bfloat162float(hi));
    }
}

// ------------------------- double-buffered fp32 GEMM (encoder projection) -----------
#define GBM 64
#define GBN 128
#define GBK 32
__global__ void __launch_bounds__(256) gemm_abt(
    const float* __restrict__ A, const float* __restrict__ W,
    const float* __restrict__ bias, float* __restrict__ C,
    int M, int N, int K, int ldC) {
    __shared__ float As[2][GBK][GBM];
    __shared__ float Bs[2][GBK][GBN];

    const int tid = threadIdx.x;
    const int tx = tid & 15, ty = tid >> 4;
    const int mBase = blockIdx.y * GBM;
    const int nBase = blockIdx.x * GBN;

    const int ar0 = (tid) >> 3,        akq0 = tid & 7;
    const int ar1 = (tid + 256) >> 3,  akq1 = tid & 7;
    float acc[4][8];
    #pragma unroll
    for (int i = 0; i < 4; i++)
        #pragma unroll
        for (int j = 0; j < 8; j++) acc[i][j] = 0.0f;

    float4 ra[2], rb[4];

    #define LOAD_TILE(k0)                                                                 \
        do {                                                                              \
            ra[0] = *reinterpret_cast<const float4*>(&A[(size_t)(mBase + ar0) * K + (k0) + akq0 * 4]); \
            ra[1] = *reinterpret_cast<const float4*>(&A[(size_t)(mBase + ar1) * K + (k0) + akq1 * 4]); \
            _Pragma("unroll")                                                             \
            for (int i = 0; i < 4; i++) {                                                 \
                int f4 = tid + 256 * i; int r = f4 >> 3, kq = f4 & 7;                     \
                rb[i] = *reinterpret_cast<const float4*>(&W[(size_t)(nBase + r) * K + (k0) + kq * 4]); \
            }                                                                             \
        } while (0)

    #define STORE_TILE(bi)                                                                \
        do {                                                                              \
            As[bi][akq0 * 4 + 0][ar0] = ra[0].x; As[bi][akq0 * 4 + 1][ar0] = ra[0].y;     \
            As[bi][akq0 * 4 + 2][ar0] = ra[0].z; As[bi][akq0 * 4 + 3][ar0] = ra[0].w;     \
            As[bi][akq1 * 4 + 0][ar1] = ra[1].x; As[bi][akq1 * 4 + 1][ar1] = ra[1].y;     \
            As[bi][akq1 * 4 + 2][ar1] = ra[1].z; As[bi][akq1 * 4 + 3][ar1] = ra[1].w;     \
            _Pragma("unroll")                                                             \
            for (int i = 0; i < 4; i++) {                                                 \
                int f4 = tid + 256 * i; int r = f4 >> 3, kq = f4 & 7;                     \
                Bs[bi][kq * 4 + 0][r] = rb[i].x; Bs[bi][kq * 4 + 1][r] = rb[i].y;         \
                Bs[bi][kq * 4 + 2][r] = rb[i].z; Bs[bi][kq * 4 + 3][r] = rb[i].w;         \
            }                                                                             \
        } while (0)

    #define COMPUTE(bi)                                                                   \
        do {                                                                              \
            _Pragma("unroll")                                                             \
            for (int k = 0; k < GBK; k++) {                                               \
                float4 a4 = *reinterpret_cast<const float4*>(&As[bi][k][ty * 4]);         \
                float4 b0 = *reinterpret_cast<const float4*>(&Bs[bi][k][tx * 8]);         \
                float4 b1 = *reinterpret_cast<const float4*>(&Bs[bi][k][tx * 8 + 4]);     \
                float a[4] = {a4.x, a4.y, a4.z, a4.w};                                    \
                float b[8] = {b0.x, b0.y, b0.z, b0.w, b1.x, b1.y, b1.z, b1.w};            \
                _Pragma("unroll")                                                         \
                for (int i = 0; i < 4; i++)                                               \
                    _Pragma("unroll")                                                     \
                    for (int j = 0; j < 8; j++) acc[i][j] = fmaf(a[i], b[j], acc[i][j]);  \
            }                                                                             \
        } while (0)

    const int nIter = K / GBK;
    LOAD_TILE(0);
    STORE_TILE(0);
    __syncthreads();
    int buf = 0;
    for (int it = 1; it < nIter; it++) {
        LOAD_TILE(it * GBK);
        COMPUTE(buf);
        STORE_TILE(buf ^ 1);
        __syncthreads();
        buf ^= 1;
    }
    COMPUTE(buf);

    #pragma unroll
    for (int i = 0; i < 4; i++) {
        size_t row = (size_t)(mBase + ty * 4 + i);
        #pragma unroll
        for (int j = 0; j < 8; j++) {
            int col = nBase + tx * 8 + j;
            C[row * (size_t)ldC + col] = acc[i][j] + bias[col];
        }
    }
}

// ------------------------- gates GEMM: fused gather + fused final argmax ------------
// grid (H4/GBN=8, KSPLIT_G, 2), 256 thr. k-slices (128 wide) align with region bounds.
// emb-region blocks (kBegin in [512,768)) first reduce the per-tile argmax partials.
__global__ void __launch_bounds__(256) gates_gemm(const float* __restrict__ embt) {
    const int dz = blockIdx.z;
    const int ks = blockIdx.y;
    const int kBegin = ks * (H4 / KSPLIT_G);
    const float* __restrict__ W = g_Wcat + (size_t)dz * H4 * H4;
    float* __restrict__ C = g_Gp + (size_t)ks * 2 * B * H4 + (size_t)dz * B * H4;

    __shared__ float As[2][GBK][GBM];
    __shared__ float Bs[2][GBK][GBN];
    __shared__ int   xs[B];
    __shared__ float pvs[256];
    __shared__ int   pis[256];

    const int tid = threadIdx.x;
    const int tx = tid & 15, ty = tid >> 4;
    const int nBase = blockIdx.x * GBN;

    const int ar0 = (tid) >> 3,        akq0 = tid & 7;
    const int ar1 = (tid + 256) >> 3,  akq1 = tid & 7;

    const bool need_x = (kBegin >= H2) && (kBegin < H3);
    if (need_x) {
        // final argmax reduce: 4 threads per batch scan 250 tiles (ascending idx)
        int bb = tid & 63, part = tid >> 6;
        float bv = -INFINITY; int bi = 0x7fffffff;
        for (int tl = part; tl < NVT; tl += 4) {
            float v = g_pval[bb * NVT + tl];
            int ix = g_pidx[bb * NVT + tl];
            if (v > bv || (v == bv && ix < bi)) { bv = v; bi = ix; }
        }
        pvs[tid] = bv; pis[tid] = bi;
        __syncthreads();
        if (part == 0) {
            #pragma unroll
            for (int p2 = 1; p2 < 4; p2++) {
                float v = pvs[tid + 64 * p2]; int ix = pis[tid + 64 * p2];
                if (v > bv || (v == bv && ix < bi)) { bv = v; bi = ix; }
            }
            xs[bb] = bi;
        }
        __syncthreads();
    }

    // region-resolved A row pointers (row = batch)
    const float* aptr0;
    const float* aptr1;
    if (kBegin < H2) {
        aptr0 = g_ctx + (size_t)ar0 * H2 + kBegin;
        aptr1 = g_ctx + (size_t)ar1 * H2 + kBegin;
    } else if (need_x) {
        aptr0 = embt + (size_t)xs[ar0] * H + (kBegin - H2);
        aptr1 = embt + (size_t)xs[ar1] * H + (kBegin - H2);
    } else {
        aptr0 = g_h + ((size_t)dz * B + ar0) * H + (kBegin - H3);
        aptr1 = g_h + ((size_t)dz * B + ar1) * H + (kBegin - H3);
    }

    float acc[4][8];
    #pragma unroll
    for (int i = 0; i < 4; i++)
        #pragma unroll
        for (int j = 0; j < 8; j++) acc[i][j] = 0.0f;

    float4 ra[2], rb[4];

    #define GLOAD_TILE(koff)                                                              \
        do {                                                                              \
            ra[0] = *reinterpret_cast<const float4*>(aptr0 + (koff) + akq0 * 4);          \
            ra[1] = *reinterpret_cast<const float4*>(aptr1 + (koff) + akq1 * 4);          \
            _Pragma("unroll")                                                             \
            for (int i = 0; i < 4; i++) {                                                 \
                int f4 = tid + 256 * i; int r = f4 >> 3, kq = f4 & 7;                     \
                rb[i] = *reinterpret_cast<const float4*>(&W[(size_t)(nBase + r) * H4 + kBegin + (koff) + kq * 4]); \
            }                                                                             \
        } while (0)

    const int nIter = (H4 / KSPLIT_G) / GBK;   // 4
    GLOAD_TILE(0);
    STORE_TILE(0);
    __syncthreads();
    int buf = 0;
    for (int it = 1; it < nIter; it++) {
        GLOAD_TILE(it * GBK);
        COMPUTE(buf);
        STORE_TILE(buf ^ 1);
        __syncthreads();
        buf ^= 1;
    }
    COMPUTE(buf);

    #pragma unroll
    for (int i = 0; i < 4; i++) {
        size_t row = (size_t)(ty * 4 + i);
        #pragma unroll
        for (int j = 0; j < 8; j++) {
            int col = nBase + tx * 8 + j;
            float bj = (ks == 0) ? g_bcat[dz * H4 + col] : 0.0f;
            C[row * H4 + col] = acc[i][j] + bj;
        }
    }
    #undef GLOAD_TILE
    #undef LOAD_TILE
    #undef STORE_TILE
    #undef COMPUTE
}

// ------------------------- attention, stage 1: qU = h_f @ UwS.T + Ub -------------------------
__global__ void __launch_bounds__(256) attn_qU_kernel(const float* __restrict__ Ub) {
    __shared__ float h_s[H];
    int b = blockIdx.y, tid = threadIdx.x;
    int j0 = blockIdx.x * 64;
    if (tid < H) h_s[tid] = g_h[(size_t)b * H + tid];
    __syncthreads();
    int warp = tid >> 5, lane = tid & 31;
    #pragma unroll
    for (int jj = 0; jj < 8; jj++) {
        int j = j0 + warp * 8 + jj;
        const float* u = g_UwS + (size_t)j * H;
        float s = 0.0f;
        #pragma unroll
        for (int k = lane; k < H; k += 32) s += u[k] * h_s[k];
        s = warpsum(s);
        if (lane == 0) g_qU[(size_t)b * H2 + j] = s + Ub[j];
    }
}

// ------------------------- attention, stage 2: scores -------------------------
__global__ void __launch_bounds__(256) attn_score_kernel(const float* __restrict__ Vw,
                                                         const float* __restrict__ Vb) {
    __shared__ float qs[H2], vs[H2];
    int b = blockIdx.y, tid = threadIdx.x;
    for (int j = tid; j < H2; j += 256) { qs[j] = g_qU[(size_t)b * H2 + j]; vs[j] = Vw[j]; }
    __syncthreads();
    int warp = tid >> 5, lane = tid & 31;
    float vb = Vb[0];
    #pragma unroll
    for (int i = 0; i < 2; i++) {
        int s = blockIdx.x * 16 + i * 8 + warp;
        const float* ep = g_encp + ((size_t)b * S + s) * H2;
        float acc = 0.0f;
        #pragma unroll 4
        for (int j = lane; j < H2; j += 32) acc += vs[j] * tanhf(qs[j] + ep[j]);
        acc = warpsum(acc);
        if (lane == 0) g_score[(size_t)b * S + s] = acc + vb;
    }
}

// ------------------------- attention, stage 3: softmax + context -------------------------
__global__ void __launch_bounds__(128) attn_ctx_kernel(const float* __restrict__ enc) {
    __shared__ float w[S];
    __shared__ float redm[4], reds[4];
    int b = blockIdx.y, tid = threadIdx.x;
    int warp = tid >> 5, lane = tid & 31;

    float sc = g_score[(size_t)b * S + tid];
    float m = warpmax(sc);
    if (lane == 0) redm[warp] = m;
    __syncthreads();
    float mx = fmaxf(fmaxf(redm[0], redm[1]), fmaxf(redm[2], redm[3]));
    float e = expf(sc - mx);
    float su = warpsum(e);
    if (lane == 0) reds[warp] = su;
    __syncthreads();
    float inv = 1.0f / (reds[0] + reds[1] + reds[2] + reds[3]);
    w[tid] = e * inv;
    __syncthreads();

    int d = blockIdx.x * 128 + tid;
    const float* eb = enc + (size_t)b * S * H2 + d;
    float acc = 0.0f;
    #pragma unroll 8
    for (int s = 0; s < S; s++) acc += w[s] * eb[(size_t)s * H2];
    g_ctx[(size_t)b * H2 + d] = acc;
}

// ------------------------- LSTM activation (+ hi/lo split of out) -------------------
__global__ void lstm_act_kernel() {
    int idx = blockIdx.x * blockDim.x + threadIdx.x;
    if (idx >= 2 * B * H) return;
    int d = idx / (B * H);
    int b = (idx / H) % B;
    int k = idx % H;
    size_t base = ((size_t)d * B + b) * H4;
    float gi = 0, gf = 0, gg = 0, go = 0;
    #pragma unroll
    for (int s = 0; s < KSPLIT_G; s++) {
        const float* Gp = g_Gp + (size_t)s * 2 * B * H4 + base;
        gi += Gp[k]; gf += Gp[H + k]; gg += Gp[2 * H + k]; go += Gp[3 * H + k];
    }
    float c_old = g_c[idx];
    float c2 = sigf(gf) * c_old + sigf(gi) * tanhf(gg);
    float h2 = sigf(go) * tanhf(c2);
    g_c[idx] = c2;
    g_h[idx] = h2;
    int o = b * H2 + d * H + k;
    __nv_bfloat16 hi = __float2bfloat16(h2);
    g_out_hi[o] = hi;
    g_out_lo[o] = __float2bfloat16(h2 - __bfloat162float(hi));
}

// ------------------------- vocab GEMM: mma.sync bf16x3 + fused partial argmax -------
#define VSM_DYN (98304 + 1024)

__device__ __forceinline__ void vissue_chunk(uint32_t tb, int v0, int c, int buf, int tid) {
    const uint32_t AHI = tb + buf * 16384u, ALO = tb + 32768u + buf * 16384u;
    const uint32_t BHI = tb + 65536u + buf * 8192u, BLO = tb + 81920u + buf * 8192u;
    #pragma unroll
    for (int i = 0; i < 4; i++) {
        int idx = tid + 256 * i;
        int r = idx >> 3, q = idx & 7;
        size_t g = (size_t)(v0 + r) * H2 + c * 64 + q * 8;
        uint32_t so = SWZ((uint32_t)(r * 128 + q * 16));
        CP16(AHI + so, (const char*)(g_Fw_hi + g));
        CP16(ALO + so, (const char*)(g_Fw_lo + g));
    }
    #pragma unroll
    for (int i = 0; i < 2; i++) {
        int idx = tid + 256 * i;
        int r = idx >> 3, q = idx & 7;
        size_t g = (size_t)r * H2 + c * 64 + q * 8;
        uint32_t so = SWZ((uint32_t)(r * 128 + q * 16));
        CP16(BHI + so, (const char*)(g_out_hi + g));
        CP16(BLO + so, (const char*)(g_out_lo + g));
    }
    CP_COMMIT();
}

__global__ void __launch_bounds__(256, 2) vocab_kernel(const float* __restrict__ Fb,
                                                       float* __restrict__ yt) {
    extern __shared__ char dsm[];
    uint32_t sb0 = smem_u32(dsm);
    uint32_t tb = (sb0 + 1023) & ~1023u;
    char* base = dsm + (tb - sb0);

    const int tid = threadIdx.x;
    const int wid = tid >> 5, lane = tid & 31;
    const int v0 = blockIdx.x * 128;
    const int wm = wid * 16;

    const int a_row = wm + (lane & 7) + ((lane >> 3) & 1) * 8;
    const int a_kb  = (lane >> 4) * 16;
    const int b_rowi = (lane & 7) + (lane >> 4) * 8;
    const int b_kb  = ((lane >> 3) & 1) * 16;

    float acc[8][4];
    #pragma unroll
    for (int i = 0; i < 8; i++)
        #pragma unroll
        for (int j = 0; j < 4; j++) acc[i][j] = 0.0f;

    vissue_chunk(tb, v0, 0, 0, tid);
    vissue_chunk(tb, v0, 1, 1, tid);

    for (int c = 0; c < 8; c++) {
        const int buf = c & 1;
        if (c < 7) { CP_WAIT(1); } else { CP_WAIT(0); }
        __syncthreads();

        const uint32_t AHI = tb + buf * 16384u, ALO = tb + 32768u + buf * 16384u;
        const uint32_t BHI = tb + 65536u + buf * 8192u, BLO = tb + 81920u + buf * 8192u;

        #pragma unroll
        for (int ks = 0; ks < 4; ks++) {
            uint32_t ah[4], al[4];
            uint32_t aoff = SWZ((uint32_t)(a_row * 128 + ks * 32 + a_kb));
            ldsm4(ah, AHI + aoff);
            ldsm4(al, ALO + aoff);
            #pragma unroll
            for (int p = 0; p < 4; p++) {
                uint32_t bh[4], bl[4];
                uint32_t boff = SWZ((uint32_t)((b_rowi + p * 16) * 128 + ks * 32 + b_kb));
                ldsm4(bh, BHI + boff);
                ldsm4(bl, BLO + boff);
                mma16816(acc[2 * p],     ah, bh);
                mma16816(acc[2 * p],     al, bh);
                mma16816(acc[2 * p],     ah, bl);
                mma16816(acc[2 * p + 1], ah, bh + 2);
                mma16816(acc[2 * p + 1], al, bh + 2);
                mma16816(acc[2 * p + 1], ah, bl + 2);
            }
        }
        __syncthreads();
        if (c < 6) vissue_chunk(tb, v0, c + 2, buf, tid);
    }

    // epilogue: transpose via smem
    float* tr = (float*)base;   // [64 batch][132]
    {
        const int m0 = wm + (lane >> 2);
        const int nb = 2 * (lane & 3);
        #pragma unroll
        for (int nt = 0; nt < 8; nt++) {
            int n = nt * 8 + nb;
            tr[n * 132 + m0]           = acc[nt][0];
            tr[(n + 1) * 132 + m0]     = acc[nt][1];
            tr[n * 132 + m0 + 8]       = acc[nt][2];
            tr[(n + 1) * 132 + m0 + 8] = acc[nt][3];
        }
    }
    __syncthreads();

    // store with bias + per-(tile,b) argmax partial (first-index tie-break)
    float* pm = tr + 64 * 132;
    int*   pi = (int*)(pm + 256);
    {
        const int bb = tid >> 2;      // batch
        const int t4 = tid & 3;
        float bestv = -INFINITY; int besti = 0x7fffffff;
        #pragma unroll
        for (int i = 0; i < 8; i++) {
            int j = t4 * 8 + i;       // float4 index, ascending v within thread
            float4 fb4 = *reinterpret_cast<const float4*>(&Fb[v0 + 4 * j]);
            float4 t = *reinterpret_cast<const float4*>(&tr[bb * 132 + 4 * j]);
            float4 r;
            r.x = t.x + fb4.x; r.y = t.y + fb4.y; r.z = t.z + fb4.z; r.w = t.w + fb4.w;
            *reinterpret_cast<float4*>(&yt[(size_t)bb * T * V + v0 + 4 * j]) = r;
            int vbase = v0 + 4 * j;
            if (r.x > bestv) { bestv = r.x; besti = vbase; }
            if (r.y > bestv) { bestv = r.y; besti = vbase + 1; }
            if (r.z > bestv) { bestv = r.z; besti = vbase + 2; }
            if (r.w > bestv) { bestv = r.w; besti = vbase + 3; }
        }
        pm[tid] = bestv; pi[tid] = besti;
    }
    __syncthreads();
    if ((tid & 3) == 0) {
        float bv = pm[tid]; int bi = pi[tid];
        #pragma unroll
        for (int t = 1; t < 4; t++) {        // ascending t4 = ascending v
            float v2 = pm[tid + t];
            if (v2 > bv) { bv = v2; bi = pi[tid + t]; }
        }
        int bb = tid >> 2;
        g_pval[bb * NVT + blockIdx.x] = bv;
        g_pidx[bb * NVT + blockIdx.x] = bi;
    }
}

// ------------------------- tail: hT, cT -------------------------
__global__ void tail_kernel(float* __restrict__ out) {
    int idx = blockIdx.x * blockDim.x + threadIdx.x;
    if (idx < 2 * B * H) {
        out[(size_t)B * T * V + idx] = g_h[idx];
        out[(size_t)B * T * V + 2 * B * H + idx] = g_c[idx];
    }
}

// ------------------------- host -------------------------
extern "C" void kernel_launch(void* const* d_in, const int* in_sizes, int n_in,
                              void* d_out, int out_size) {
    const float* enc   = (const float*)d_in[0];
    const float* h0    = (const float*)d_in[1];
    const float* c0    = (const float*)d_in[2];
    const float* Uw    = (const float*)d_in[3];
    const float* Ub    = (const float*)d_in[4];
    const float* Ww    = (const float*)d_in[5];
    const float* Wb    = (const float*)d_in[6];
    const float* Vw    = (const float*)d_in[7];
    const float* Vb    = (const float*)d_in[8];
    const float* Wih_f = (const float*)d_in[9];
    const float* Whh_f = (const float*)d_in[10];
    const float* b_f   = (const float*)d_in[11];
    const float* Wih_b = (const float*)d_in[12];
    const float* Whh_b = (const float*)d_in[13];
    const float* b_b   = (const float*)d_in[14];
    const float* Fw    = (const float*)d_in[15];
    const float* Fb    = (const float*)d_in[16];
    const float* embt  = (const float*)d_in[17];
    (void)in_sizes; (void)n_in;
    float* out = (float*)d_out;

    static bool attr_set = false;
    if (!attr_set) {
        cudaFuncSetAttribute(vocab_kernel, cudaFuncAttributeMaxDynamicSharedMemorySize, VSM_DYN);
        attr_set = true;
    }

    // one-time packing + state init
    pack_kernel<<<2048, 1024>>>(Uw, Wih_f, Whh_f, b_f, Wih_b, Whh_b, b_b, h0, c0);
    pack_fw_kernel<<<4096, 256>>>(Fw);

    // enc_proj = enc @ Ww.T + Wb
    {
        float* encp;  cudaGetSymbolAddress((void**)&encp, g_encp);
        gemm_abt<<<dim3(H2 / GBN, (B * S) / GBM, 1), 256>>>(
            enc, Ww, Wb, encp, B * S, H2, H2, H2);
    }

    for (int t = 0; t < T; t++) {
        attn_qU_kernel<<<dim3(8, B), 256>>>(Ub);
        attn_score_kernel<<<dim3(8, B), 256>>>(Vw, Vb);
        attn_ctx_kernel<<<dim3(4, B), 128>>>(enc);
        gates_gemm<<<dim3(H4 / GBN, KSPLIT_G, 2), 256>>>(embt);
        lstm_act_kernel<<<(2 * B * H) / 256, 256>>>();
        vocab_kernel<<<NVT, 256, VSM_DYN>>>(Fb, out + (size_t)t * V);
    }

    if (out_size >= B * T * V + 4 * B * H)
        tail_kernel<<<(2 * B * H + 255) / 256, 256>>>(out);
}

// round 9
// speedup vs baseline: 1.1157x; 1.0807x over previous
#include <cuda_runtime.h>
#include <cuda_bf16.h>
#include <math.h>
#include <stdint.h>

// Problem dims (fixed)
#define B   64
#define S   128
#define H   256
#define H2  512
#define H3  768
#define H4  1024
#define V   32000
#define T   32
#define NVT 250        // vocab tiles = V/128

#define KSPLIT_G 8     // gates GEMM k-split

// ------------------------- scratch (static device globals) -------------------------
__device__ float g_encp[B * S * H2];          // enc @ Ww.T + Wb   (16.8 MB)
__device__ float g_UwS[H2 * H];               // Uw[:, :H] + Uw[:, H:]
__device__ float g_qU[B * H2];                // h_f @ UwS.T + Ub
__device__ float g_score[B * S];              // raw attention scores
__device__ float g_ctx[B * H2];               // attention context
__device__ float g_Wcat[2 * H4 * H4];         // [Wih | Whh] per direction (8 MB)
__device__ float g_bcat[2 * H4];
__device__ float g_Gp[KSPLIT_G * 2 * B * H4]; // split-K partial gate sums (4 MB)
__device__ float g_h[2 * B * H];
__device__ float g_c[2 * B * H];
__device__ float g_pval[B * NVT];             // per-(batch,tile) argmax partials
__device__ int   g_pidx[B * NVT];
// bf16x3 split operands for the vocab GEMM
__device__ __nv_bfloat16 g_Fw_hi[(size_t)V * H2];   // 32.8 MB
__device__ __nv_bfloat16 g_Fw_lo[(size_t)V * H2];   // 32.8 MB
__device__ __nv_bfloat16 g_out_hi[B * H2];
__device__ __nv_bfloat16 g_out_lo[B * H2];

__device__ __forceinline__ float warpsum(float v) {
    #pragma unroll
    for (int o = 16; o > 0; o >>= 1) v += __shfl_xor_sync(0xffffffffu, v, o);
    return v;
}
__device__ __forceinline__ float warpmax(float v) {
    #pragma unroll
    for (int o = 16; o > 0; o >>= 1) v = fmaxf(v, __shfl_xor_sync(0xffffffffu, v, o));
    return v;
}
__device__ __forceinline__ float sigf(float x) { return 1.0f / (1.0f + expf(-x)); }

// ------------------------- portable PTX helpers (sm_80+ baseline) -------------------
__device__ __forceinline__ uint32_t smem_u32(const void* p) {
    uint32_t a;
    asm("{ .reg .u64 t; cvta.to.shared.u64 t, %1; cvt.u32.u64 %0, t; }" : "=r"(a) : "l"(p));
    return a;
}
#define SWZ(x) ((x) ^ (((x) >> 3) & 0x70))

#define CP16(saddr, gptr) \
    asm volatile("cp.async.cg.shared.global [%0], [%1], 16;" :: "r"(saddr), "l"(gptr))
#define CP_COMMIT() asm volatile("cp.async.commit_group;" ::: "memory")
#define CP_WAIT(n)  asm volatile("cp.async.wait_group %0;" :: "n"(n) : "memory")

__device__ __forceinline__ void ldsm4(uint32_t* r, uint32_t addr) {
    asm volatile("ldmatrix.sync.aligned.m8n8.x4.shared.b16 {%0,%1,%2,%3}, [%4];"
        : "=r"(r[0]), "=r"(r[1]), "=r"(r[2]), "=r"(r[3]) : "r"(addr));
}
__device__ __forceinline__ void mma16816(float* c, const uint32_t* a, const uint32_t* b) {
    asm volatile("mma.sync.aligned.m16n8k16.row.col.f32.bf16.bf16.f32 "
        "{%0,%1,%2,%3}, {%4,%5,%6,%7}, {%8,%9}, {%0,%1,%2,%3};"
        : "+f"(c[0]), "+f"(c[1]), "+f"(c[2]), "+f"(c[3])
        : "r"(a[0]), "r"(a[1]), "r"(a[2]), "r"(a[3]), "r"(b[0]), "r"(b[1]));
}

// ------------------------- one-time pack / init -------------------------
__global__ void pack_kernel(const float* __restrict__ Uw,
                            const float* __restrict__ Wih_f, const float* __restrict__ Whh_f,
                            const float* __restrict__ b_f,
                            const float* __restrict__ Wih_b, const float* __restrict__ Whh_b,
                            const float* __restrict__ b_b,
                            const float* __restrict__ h0, const float* __restrict__ c0) {
    const size_t NTOT = (size_t)2 * H4 * H4;  // 2,097,152
    for (size_t idx = (size_t)blockIdx.x * blockDim.x + threadIdx.x; idx < NTOT;
         idx += (size_t)gridDim.x * blockDim.x) {
        size_t d = idx >> 20;
        size_t r = (idx >> 10) & 1023;
        size_t k = idx & 1023;
        const float* Wih = d ? Wih_b : Wih_f;
        const float* Whh = d ? Whh_b : Whh_f;
        g_Wcat[idx] = (k < H3) ? Wih[r * H3 + k] : Whh[r * H + (k - H3)];

        if (idx < (size_t)H2 * H) {
            size_t j = idx >> 8, kk = idx & 255;
            g_UwS[idx] = Uw[j * H2 + kk] + Uw[j * H2 + H + kk];
        }
        if (idx < 2 * H4) g_bcat[idx] = (idx < H4) ? b_f[idx] : b_b[idx - H4];
        if (idx < 2 * B * H) { g_h[idx] = h0[idx]; g_c[idx] = c0[idx]; }
        // argmax partials: step 0 must resolve to token 0 (x0 = zeros)
        if (idx < (size_t)B * NVT) {
            int tl = (int)(idx % NVT);
            g_pval[idx] = (tl == 0) ? 0.0f : -INFINITY;
            g_pidx[idx] = (tl == 0) ? 0 : 0x7fffffff;
        }
    }
}

// split Fw into hi/lo bf16 once
__global__ void pack_fw_kernel(const float* __restrict__ Fw) {
    const size_t NTOT = (size_t)V * H2;
    for (size_t i = (size_t)blockIdx.x * blockDim.x + threadIdx.x; i < NTOT;
         i += (size_t)gridDim.x * blockDim.x) {
        float v = Fw[i];
        __nv_bfloat16 hi = __float2bfloat16(v);
        g_Fw_hi[i] = hi;
        g_Fw_lo[i] = __float2bfloat16(v - __bfloat162float(hi));
    }
}

// ------------------------- double-buffered fp32 GEMM (encoder projection) -----------
#define GBM 64
#define GBN 128
#define GBK 32
__global__ void __launch_bounds__(256) gemm_abt(
    const float* __restrict__ A, const float* __restrict__ W,
    const float* __restrict__ bias, float* __restrict__ C,
    int M, int N, int K, int ldC) {
    __shared__ float As[2][GBK][GBM];
    __shared__ float Bs[2][GBK][GBN];

    const int tid = threadIdx.x;
    const int tx = tid & 15, ty = tid >> 4;
    const int mBase = blockIdx.y * GBM;
    const int nBase = blockIdx.x * GBN;

    const int ar0 = (tid) >> 3,        akq0 = tid & 7;
    const int ar1 = (tid + 256) >> 3,  akq1 = tid & 7;
    float acc[4][8];
    #pragma unroll
    for (int i = 0; i < 4; i++)
        #pragma unroll
        for (int j = 0; j < 8; j++) acc[i][j] = 0.0f;

    float4 ra[2], rb[4];

    #define LOAD_TILE(k0)                                                                 \
        do {                                                                              \
            ra[0] = *reinterpret_cast<const float4*>(&A[(size_t)(mBase + ar0) * K + (k0) + akq0 * 4]); \
            ra[1] = *reinterpret_cast<const float4*>(&A[(size_t)(mBase + ar1) * K + (k0) + akq1 * 4]); \
            _Pragma("unroll")                                                             \
            for (int i = 0; i < 4; i++) {                                                 \
                int f4 = tid + 256 * i; int r = f4 >> 3, kq = f4 & 7;                     \
                rb[i] = *reinterpret_cast<const float4*>(&W[(size_t)(nBase + r) * K + (k0) + kq * 4]); \
            }                                                                             \
        } while (0)

    #define STORE_TILE(bi)                                                                \
        do {                                                                              \
            As[bi][akq0 * 4 + 0][ar0] = ra[0].x; As[bi][akq0 * 4 + 1][ar0] = ra[0].y;     \
            As[bi][akq0 * 4 + 2][ar0] = ra[0].z; As[bi][akq0 * 4 + 3][ar0] = ra[0].w;     \
            As[bi][akq1 * 4 + 0][ar1] = ra[1].x; As[bi][akq1 * 4 + 1][ar1] = ra[1].y;     \
            As[bi][akq1 * 4 + 2][ar1] = ra[1].z; As[bi][akq1 * 4 + 3][ar1] = ra[1].w;     \
            _Pragma("unroll")                                                             \
            for (int i = 0; i < 4; i++) {                                                 \
                int f4 = tid + 256 * i; int r = f4 >> 3, kq = f4 & 7;                     \
                Bs[bi][kq * 4 + 0][r] = rb[i].x; Bs[bi][kq * 4 + 1][r] = rb[i].y;         \
                Bs[bi][kq * 4 + 2][r] = rb[i].z; Bs[bi][kq * 4 + 3][r] = rb[i].w;         \
            }                                                                             \
        } while (0)

    #define COMPUTE(bi)                                                                   \
        do {                                                                              \
            _Pragma("unroll")                                                             \
            for (int k = 0; k < GBK; k++) {                                               \
                float4 a4 = *reinterpret_cast<const float4*>(&As[bi][k][ty * 4]);         \
                float4 b0 = *reinterpret_cast<const float4*>(&Bs[bi][k][tx * 8]);         \
                float4 b1 = *reinterpret_cast<const float4*>(&Bs[bi][k][tx * 8 + 4]);     \
                float a[4] = {a4.x, a4.y, a4.z, a4.w};                                    \
                float b[8] = {b0.x, b0.y, b0.z, b0.w, b1.x, b1.y, b1.z, b1.w};            \
                _Pragma("unroll")                                                         \
                for (int i = 0; i < 4; i++)                                               \
                    _Pragma("unroll")                                                     \
                    for (int j = 0; j < 8; j++) acc[i][j] = fmaf(a[i], b[j], acc[i][j]);  \
            }                                                                             \
        } while (0)

    const int nIter = K / GBK;
    LOAD_TILE(0);
    STORE_TILE(0);
    __syncthreads();
    int buf = 0;
    for (int it = 1; it < nIter; it++) {
        LOAD_TILE(it * GBK);
        COMPUTE(buf);
        STORE_TILE(buf ^ 1);
        __syncthreads();
        buf ^= 1;
    }
    COMPUTE(buf);

    #pragma unroll
    for (int i = 0; i < 4; i++) {
        size_t row = (size_t)(mBase + ty * 4 + i);
        #pragma unroll
        for (int j = 0; j < 8; j++) {
            int col = nBase + tx * 8 + j;
            C[row * (size_t)ldC + col] = acc[i][j] + bias[col];
        }
    }
}

// ------------------------- gates GEMM: fused gather + fused final argmax ------------
__global__ void __launch_bounds__(256) gates_gemm(const float* __restrict__ embt) {
    const int dz = blockIdx.z;
    const int ks = blockIdx.y;
    const int kBegin = ks * (H4 / KSPLIT_G);
    const float* __restrict__ W = g_Wcat + (size_t)dz * H4 * H4;
    float* __restrict__ C = g_Gp + (size_t)ks * 2 * B * H4 + (size_t)dz * B * H4;

    __shared__ float As[2][GBK][GBM];
    __shared__ float Bs[2][GBK][GBN];
    __shared__ int   xs[B];
    __shared__ float pvs[256];
    __shared__ int   pis[256];

    const int tid = threadIdx.x;
    const int tx = tid & 15, ty = tid >> 4;
    const int nBase = blockIdx.x * GBN;

    const int ar0 = (tid) >> 3,        akq0 = tid & 7;
    const int ar1 = (tid + 256) >> 3,  akq1 = tid & 7;

    const bool need_x = (kBegin >= H2) && (kBegin < H3);
    if (need_x) {
        int bb = tid & 63, part = tid >> 6;
        float bv = -INFINITY; int bi = 0x7fffffff;
        for (int tl = part; tl < NVT; tl += 4) {
            float v = g_pval[bb * NVT + tl];
            int ix = g_pidx[bb * NVT + tl];
            if (v > bv || (v == bv && ix < bi)) { bv = v; bi = ix; }
        }
        pvs[tid] = bv; pis[tid] = bi;
        __syncthreads();
        if (part == 0) {
            #pragma unroll
            for (int p2 = 1; p2 < 4; p2++) {
                float v = pvs[tid + 64 * p2]; int ix = pis[tid + 64 * p2];
                if (v > bv || (v == bv && ix < bi)) { bv = v; bi = ix; }
            }
            xs[bb] = bi;
        }
        __syncthreads();
    }

    const float* aptr0;
    const float* aptr1;
    if (kBegin < H2) {
        aptr0 = g_ctx + (size_t)ar0 * H2 + kBegin;
        aptr1 = g_ctx + (size_t)ar1 * H2 + kBegin;
    } else if (need_x) {
        aptr0 = embt + (size_t)xs[ar0] * H + (kBegin - H2);
        aptr1 = embt + (size_t)xs[ar1] * H + (kBegin - H2);
    } else {
        aptr0 = g_h + ((size_t)dz * B + ar0) * H + (kBegin - H3);
        aptr1 = g_h + ((size_t)dz * B + ar1) * H + (kBegin - H3);
    }

    float acc[4][8];
    #pragma unroll
    for (int i = 0; i < 4; i++)
        #pragma unroll
        for (int j = 0; j < 8; j++) acc[i][j] = 0.0f;

    float4 ra[2], rb[4];

    #define GLOAD_TILE(koff)                                                              \
        do {                                                                              \
            ra[0] = *reinterpret_cast<const float4*>(aptr0 + (koff) + akq0 * 4);          \
            ra[1] = *reinterpret_cast<const float4*>(aptr1 + (koff) + akq1 * 4);          \
            _Pragma("unroll")                                                             \
            for (int i = 0; i < 4; i++) {                                                 \
                int f4 = tid + 256 * i; int r = f4 >> 3, kq = f4 & 7;                     \
                rb[i] = *reinterpret_cast<const float4*>(&W[(size_t)(nBase + r) * H4 + kBegin + (koff) + kq * 4]); \
            }                                                                             \
        } while (0)

    const int nIter = (H4 / KSPLIT_G) / GBK;   // 4
    GLOAD_TILE(0);
    STORE_TILE(0);
    __syncthreads();
    int buf = 0;
    for (int it = 1; it < nIter; it++) {
        GLOAD_TILE(it * GBK);
        COMPUTE(buf);
        STORE_TILE(buf ^ 1);
        __syncthreads();
        buf ^= 1;
    }
    COMPUTE(buf);

    #pragma unroll
    for (int i = 0; i < 4; i++) {
        size_t row = (size_t)(ty * 4 + i);
        #pragma unroll
        for (int j = 0; j < 8; j++) {
            int col = nBase + tx * 8 + j;
            float bj = (ks == 0) ? g_bcat[dz * H4 + col] : 0.0f;
            C[row * H4 + col] = acc[i][j] + bj;
        }
    }
    #undef GLOAD_TILE
    #undef LOAD_TILE
    #undef STORE_TILE
    #undef COMPUTE
}

// ------------------------- attention, stage 1: qU = h_f @ UwS.T + Ub ----------------
__global__ void __launch_bounds__(256) attn_qU_kernel(const float* __restrict__ Ub) {
    __shared__ float h_s[H];
    int b = blockIdx.y, tid = threadIdx.x;
    int j0 = blockIdx.x * 64;
    if (tid < H) h_s[tid] = g_h[(size_t)b * H + tid];
    __syncthreads();
    int warp = tid >> 5, lane = tid & 31;
    #pragma unroll
    for (int jj = 0; jj < 8; jj++) {
        int j = j0 + warp * 8 + jj;
        const float* u = g_UwS + (size_t)j * H;
        float s = 0.0f;
        #pragma unroll
        for (int k = lane; k < H; k += 32) s += u[k] * h_s[k];
        s = warpsum(s);
        if (lane == 0) g_qU[(size_t)b * H2 + j] = s + Ub[j];
    }
}

// ------------------------- attention, stage 2: scores -------------------------------
__global__ void __launch_bounds__(256) attn_score_kernel(const float* __restrict__ Vw,
                                                         const float* __restrict__ Vb) {
    __shared__ float qs[H2], vs[H2];
    int b = blockIdx.y, tid = threadIdx.x;
    for (int j = tid; j < H2; j += 256) { qs[j] = g_qU[(size_t)b * H2 + j]; vs[j] = Vw[j]; }
    __syncthreads();
    int warp = tid >> 5, lane = tid & 31;
    float vb = Vb[0];
    #pragma unroll
    for (int i = 0; i < 2; i++) {
        int s = blockIdx.x * 16 + i * 8 + warp;
        const float* ep = g_encp + ((size_t)b * S + s) * H2;
        float acc = 0.0f;
        #pragma unroll 4
        for (int j = lane; j < H2; j += 32) acc += vs[j] * tanhf(qs[j] + ep[j]);
        acc = warpsum(acc);
        if (lane == 0) g_score[(size_t)b * S + s] = acc + vb;
    }
}

// ------------------------- attention, stage 3: softmax + context --------------------
__global__ void __launch_bounds__(128) attn_ctx_kernel(const float* __restrict__ enc) {
    __shared__ float w[S];
    __shared__ float redm[4], reds[4];
    int b = blockIdx.y, tid = threadIdx.x;
    int warp = tid >> 5, lane = tid & 31;

    float sc = g_score[(size_t)b * S + tid];
    float m = warpmax(sc);
    if (lane == 0) redm[warp] = m;
    __syncthreads();
    float mx = fmaxf(fmaxf(redm[0], redm[1]), fmaxf(redm[2], redm[3]));
    float e = expf(sc - mx);
    float su = warpsum(e);
    if (lane == 0) reds[warp] = su;
    __syncthreads();
    float inv = 1.0f / (reds[0] + reds[1] + reds[2] + reds[3]);
    w[tid] = e * inv;
    __syncthreads();

    int d = blockIdx.x * 128 + tid;
    const float* eb = enc + (size_t)b * S * H2 + d;
    float acc = 0.0f;
    #pragma unroll 8
    for (int s = 0; s < S; s++) acc += w[s] * eb[(size_t)s * H2];
    g_ctx[(size_t)b * H2 + d] = acc;
}

// ------------------------- LSTM activation (+ hi/lo split of out) -------------------
__global__ void lstm_act_kernel() {
    int idx = blockIdx.x * blockDim.x + threadIdx.x;
    if (idx >= 2 * B * H) return;
    int d = idx / (B * H);
    int b = (idx / H) % B;
    int k = idx % H;
    size_t base = ((size_t)d * B + b) * H4;
    float gi = 0, gf = 0, gg = 0, go = 0;
    #pragma unroll
    for (int s = 0; s < KSPLIT_G; s++) {
        const float* Gp = g_Gp + (size_t)s * 2 * B * H4 + base;
        gi += Gp[k]; gf += Gp[H + k]; gg += Gp[2 * H + k]; go += Gp[3 * H + k];
    }
    float c_old = g_c[idx];
    float c2 = sigf(gf) * c_old + sigf(gi) * tanhf(gg);
    float h2 = sigf(go) * tanhf(c2);
    g_c[idx] = c2;
    g_h[idx] = h2;
    int o = b * H2 + d * H + k;
    __nv_bfloat16 hi = __float2bfloat16(h2);
    g_out_hi[o] = hi;
    g_out_lo[o] = __float2bfloat16(h2 - __bfloat162float(hi));
}

// ------------------------- vocab GEMM: mma.sync bf16x3 + fused partial argmax -------
#define VSM_DYN (98304 + 1024)

__device__ __forceinline__ void vissue_chunk(uint32_t tb, int v0, int c, int buf, int tid) {
    const uint32_t AHI = tb + buf * 16384u, ALO = tb + 32768u + buf * 16384u;
    const uint32_t BHI = tb + 65536u + buf * 8192u, BLO = tb + 81920u + buf * 8192u;
    #pragma unroll
    for (int i = 0; i < 4; i++) {
        int idx = tid + 256 * i;
        int r = idx >> 3, q = idx & 7;
        size_t g = (size_t)(v0 + r) * H2 + c * 64 + q * 8;
        uint32_t so = SWZ((uint32_t)(r * 128 + q * 16));
        CP16(AHI + so, (const char*)(g_Fw_hi + g));
        CP16(ALO + so, (const char*)(g_Fw_lo + g));
    }
    #pragma unroll
    for (int i = 0; i < 2; i++) {
        int idx = tid + 256 * i;
        int r = idx >> 3, q = idx & 7;
        size_t g = (size_t)r * H2 + c * 64 + q * 8;
        uint32_t so = SWZ((uint32_t)(r * 128 + q * 16));
        CP16(BHI + so, (const char*)(g_out_hi + g));
        CP16(BLO + so, (const char*)(g_out_lo + g));
    }
    CP_COMMIT();
}

__global__ void __launch_bounds__(256, 2) vocab_kernel(const float* __restrict__ Fb,
                                                       float* __restrict__ yt) {
    extern __shared__ char dsm[];
    uint32_t sb0 = smem_u32(dsm);
    uint32_t tb = (sb0 + 1023) & ~1023u;
    char* base = dsm + (tb - sb0);

    const int tid = threadIdx.x;
    const int wid = tid >> 5, lane = tid & 31;
    const int v0 = blockIdx.x * 128;
    const int wm = wid * 16;

    const int a_row = wm + (lane & 7) + ((lane >> 3) & 1) * 8;
    const int a_kb  = (lane >> 4) * 16;
    const int b_rowi = (lane & 7) + (lane >> 4) * 8;
    const int b_kb  = ((lane >> 3) & 1) * 16;

    float acc[8][4];
    #pragma unroll
    for (int i = 0; i < 8; i++)
        #pragma unroll
        for (int j = 0; j < 4; j++) acc[i][j] = 0.0f;

    vissue_chunk(tb, v0, 0, 0, tid);
    vissue_chunk(tb, v0, 1, 1, tid);

    for (int c = 0; c < 8; c++) {
        const int buf = c & 1;
        if (c < 7) { CP_WAIT(1); } else { CP_WAIT(0); }
        __syncthreads();

        const uint32_t AHI = tb + buf * 16384u, ALO = tb + 32768u + buf * 16384u;
        const uint32_t BHI = tb + 65536u + buf * 8192u, BLO = tb + 81920u + buf * 8192u;

        #pragma unroll
        for (int ks = 0; ks < 4; ks++) {
            uint32_t ah[4], al[4];
            uint32_t aoff = SWZ((uint32_t)(a_row * 128 + ks * 32 + a_kb));
            ldsm4(ah, AHI + aoff);
            ldsm4(al, ALO + aoff);
            #pragma unroll
            for (int p = 0; p < 4; p++) {
                uint32_t bh[4], bl[4];
                uint32_t boff = SWZ((uint32_t)((b_rowi + p * 16) * 128 + ks * 32 + b_kb));
                ldsm4(bh, BHI + boff);
                ldsm4(bl, BLO + boff);
                mma16816(acc[2 * p],     ah, bh);
                mma16816(acc[2 * p],     al, bh);
                mma16816(acc[2 * p],     ah, bl);
                mma16816(acc[2 * p + 1], ah, bh + 2);
                mma16816(acc[2 * p + 1], al, bh + 2);
                mma16816(acc[2 * p + 1], ah, bl + 2);
            }
        }
        __syncthreads();
        if (c < 6) vissue_chunk(tb, v0, c + 2, buf, tid);
    }

    // epilogue: transpose via smem
    float* tr = (float*)base;   // [64 batch][132]
    {
        const int m0 = wm + (lane >> 2);
        const int nb = 2 * (lane & 3);
        #pragma unroll
        for (int nt = 0; nt < 8; nt++) {
            int n = nt * 8 + nb;
            tr[n * 132 + m0]           = acc[nt][0];
            tr[(n + 1) * 132 + m0]     = acc[nt][1];
            tr[n * 132 + m0 + 8]       = acc[nt][2];
            tr[(n + 1) * 132 + m0 + 8] = acc[nt][3];
        }
    }
    __syncthreads();

    // store with bias + per-(tile,b) argmax partial (first-index tie-break)
    float* pm = tr + 64 * 132;
    int*   pi = (int*)(pm + 256);
    {
        const int bb = tid >> 2;      // batch
        const int t4 = tid & 3;
        float bestv = -INFINITY; int besti = 0x7fffffff;
        #pragma unroll
        for (int i = 0; i < 8; i++) {
            int j = t4 * 8 + i;       // ascending v within thread
            float4 fb4 = *reinterpret_cast<const float4*>(&Fb[v0 + 4 * j]);
            float4 t = *reinterpret_cast<const float4*>(&tr[bb * 132 + 4 * j]);
            float4 r;
            r.x = t.x + fb4.x; r.y = t.y + fb4.y; r.z = t.z + fb4.z; r.w = t.w + fb4.w;
            *reinterpret_cast<float4*>(&yt[(size_t)bb * T * V + v0 + 4 * j]) = r;
            int vbase = v0 + 4 * j;
            if (r.x > bestv) { bestv = r.x; besti = vbase; }
            if (r.y > bestv) { bestv = r.y; besti = vbase + 1; }
            if (r.z > bestv) { bestv = r.z; besti = vbase + 2; }
            if (r.w > bestv) { bestv = r.w; besti = vbase + 3; }
        }
        pm[tid] = bestv; pi[tid] = besti;
    }
    __syncthreads();
    if ((tid & 3) == 0) {
        float bv = pm[tid]; int bi = pi[tid];
        #pragma unroll
        for (int t = 1; t < 4; t++) {
            float v2 = pm[tid + t];
            if (v2 > bv) { bv = v2; bi = pi[tid + t]; }
        }
        int bb = tid >> 2;
        g_pval[bb * NVT + blockIdx.x] = bv;
        g_pidx[bb * NVT + blockIdx.x] = bi;
    }
}

// ------------------------- tail: hT, cT -------------------------
__global__ void tail_kernel(float* __restrict__ out) {
    int idx = blockIdx.x * blockDim.x + threadIdx.x;
    if (idx < 2 * B * H) {
        out[(size_t)B * T * V + idx] = g_h[idx];
        out[(size_t)B * T * V + 2 * B * H + idx] = g_c[idx];
    }
}

// ------------------------- host -------------------------
extern "C" void kernel_launch(void* const* d_in, const int* in_sizes, int n_in,
                              void* d_out, int out_size) {
    const float* enc   = (const float*)d_in[0];
    const float* h0    = (const float*)d_in[1];
    const float* c0    = (const float*)d_in[2];
    const float* Uw    = (const float*)d_in[3];
    const float* Ub    = (const float*)d_in[4];
    const float* Ww    = (const float*)d_in[5];
    const float* Wb    = (const float*)d_in[6];
    const float* Vw    = (const float*)d_in[7];
    const float* Vb    = (const float*)d_in[8];
    const float* Wih_f = (const float*)d_in[9];
    const float* Whh_f = (const float*)d_in[10];
    const float* b_f   = (const float*)d_in[11];
    const float* Wih_b = (const float*)d_in[12];
    const float* Whh_b = (const float*)d_in[13];
    const float* b_b   = (const float*)d_in[14];
    const float* Fw    = (const float*)d_in[15];
    const float* Fb    = (const float*)d_in[16];
    const float* embt  = (const float*)d_in[17];
    (void)in_sizes; (void)n_in;
    float* out = (float*)d_out;

    // one-time host-side setup (no device memory involved)
    static cudaStream_t s2;
    static cudaEvent_t evF, evJ;
    static bool init_done = false;
    if (!init_done) {
        cudaFuncSetAttribute(vocab_kernel, cudaFuncAttributeMaxDynamicSharedMemorySize, VSM_DYN);
        cudaStreamCreateWithFlags(&s2, cudaStreamNonBlocking);
        cudaEventCreateWithFlags(&evF, cudaEventDisableTiming);
        cudaEventCreateWithFlags(&evJ, cudaEventDisableTiming);
        init_done = true;
    }

    // one-time packing + state init (main stream)
    pack_kernel<<<2048, 1024>>>(Uw, Wih_f, Whh_f, b_f, Wih_b, Whh_b, b_b, h0, c0);
    pack_fw_kernel<<<4096, 256>>>(Fw);

    // enc_proj = enc @ Ww.T + Wb
    {
        float* encp;  cudaGetSymbolAddress((void**)&encp, g_encp);
        gemm_abt<<<dim3(H2 / GBN, (B * S) / GBM, 1), 256>>>(
            enc, Ww, Wb, encp, B * S, H2, H2, H2);
    }

    // attention for step 0 (main stream)
    attn_qU_kernel<<<dim3(8, B), 256>>>(Ub);
    attn_score_kernel<<<dim3(8, B), 256>>>(Vw, Vb);
    attn_ctx_kernel<<<dim3(4, B), 128>>>(enc);

    for (int t = 0; t < T; t++) {
        // main: gates (consumes ctx(t) + argmax partials(t-1)) -> act
        gates_gemm<<<dim3(H4 / GBN, KSPLIT_G, 2), 256>>>(embt);
        lstm_act_kernel<<<(2 * B * H) / 256, 256>>>();

        // fork: s2 runs attention for step t+1 concurrently with vocab(t)
        cudaEventRecord(evF, 0);
        cudaStreamWaitEvent(s2, evF, 0);

        vocab_kernel<<<NVT, 256, VSM_DYN>>>(Fb, out + (size_t)t * V);

        attn_qU_kernel<<<dim3(8, B), 256, 0, s2>>>(Ub);
        attn_score_kernel<<<dim3(8, B), 256, 0, s2>>>(Vw, Vb);
        attn_ctx_kernel<<<dim3(4, B), 128, 0, s2>>>(enc);

        // join
        cudaEventRecord(evJ, s2);
        cudaStreamWaitEvent(0, evJ, 0);
    }

    if (out_size >= B * T * V + 4 * B * H)
        tail_kernel<<<(2 * B * H + 255) / 256, 256>>>(out);
}

// round 12
// speedup vs baseline: 1.1885x; 1.0652x over previous
#include <cuda_runtime.h>
#include <cuda_bf16.h>
#include <math.h>
#include <stdint.h>

// Problem dims (fixed)
#define B   64
#define S   128
#define H   256
#define H2  512
#define H3  768
#define H4  1024
#define V   32000
#define T   32
#define NVT 250        // vocab tiles = V/128
#define MS  (B * S)    // 8192 rows of enc

#define KSPLIT_G 8     // gates GEMM k-split (fp32 path, proven)

// ------------------------- scratch (static device globals) -------------------------
__device__ float g_encp[B * S * H2];          // enc @ Ww.T + Wb   (16.8 MB)
__device__ float g_UwS[H2 * H];               // Uw[:, :H] + Uw[:, H:]
__device__ float g_qU[B * H2];                // h_f @ UwS.T + Ub
__device__ float g_score[B * S];              // raw attention scores
__device__ float g_ctx[B * H2];               // attention context (fp32)
__device__ float g_Wcat[2 * H4 * H4];         // [Wih | Whh] per direction (8 MB, fp32)
__device__ float g_bcat[2 * H4];
__device__ float g_Gp[KSPLIT_G * 2 * B * H4]; // split-K partial gate sums (4 MB)
__device__ float g_h[2 * B * H];
__device__ float g_c[2 * B * H];
__device__ float g_pval[B * NVT];             // per-(batch,tile) argmax partials
__device__ int   g_pidx[B * NVT];
// bf16x3 split operands (feed-forward GEMMs only)
__device__ __nv_bfloat16 g_Fw_hi[(size_t)V * H2];   // 32.8 MB
__device__ __nv_bfloat16 g_Fw_lo[(size_t)V * H2];   // 32.8 MB
__device__ __nv_bfloat16 g_out_hi[B * H2];
__device__ __nv_bfloat16 g_out_lo[B * H2];
__device__ __nv_bfloat16 g_enc_hi[(size_t)MS * H2]; // 8.4 MB
__device__ __nv_bfloat16 g_enc_lo[(size_t)MS * H2];
__device__ __nv_bfloat16 g_Ww_hi[H2 * H2];
__device__ __nv_bfloat16 g_Ww_lo[H2 * H2];

__device__ __forceinline__ float warpsum(float v) {
    #pragma unroll
    for (int o = 16; o > 0; o >>= 1) v += __shfl_xor_sync(0xffffffffu, v, o);
    return v;
}
__device__ __forceinline__ float warpmax(float v) {
    #pragma unroll
    for (int o = 16; o > 0; o >>= 1) v = fmaxf(v, __shfl_xor_sync(0xffffffffu, v, o));
    return v;
}
__device__ __forceinline__ float sigf(float x) { return 1.0f / (1.0f + expf(-x)); }

// ------------------------- portable PTX helpers (sm_80+ baseline) -------------------
__device__ __forceinline__ uint32_t smem_u32(const void* p) {
    uint32_t a;
    asm("{ .reg .u64 t; cvta.to.shared.u64 t, %1; cvt.u32.u64 %0, t; }" : "=r"(a) : "l"(p));
    return a;
}
#define SWZ(x) ((x) ^ (((x) >> 3) & 0x70))

#define CP16(saddr, gptr) \
    asm volatile("cp.async.cg.shared.global [%0], [%1], 16;" :: "r"(saddr), "l"(gptr))
#define CP_COMMIT() asm volatile("cp.async.commit_group;" ::: "memory")
#define CP_WAIT(n)  asm volatile("cp.async.wait_group %0;" :: "n"(n) : "memory")

__device__ __forceinline__ void ldsm4(uint32_t* r, uint32_t addr) {
    asm volatile("ldmatrix.sync.aligned.m8n8.x4.shared.b16 {%0,%1,%2,%3}, [%4];"
        : "=r"(r[0]), "=r"(r[1]), "=r"(r[2]), "=r"(r[3]) : "r"(addr));
}
__device__ __forceinline__ void mma16816(float* c, const uint32_t* a, const uint32_t* b) {
    asm volatile("mma.sync.aligned.m16n8k16.row.col.f32.bf16.bf16.f32 "
        "{%0,%1,%2,%3}, {%4,%5,%6,%7}, {%8,%9}, {%0,%1,%2,%3};"
        : "+f"(c[0]), "+f"(c[1]), "+f"(c[2]), "+f"(c[3])
        : "r"(a[0]), "r"(a[1]), "r"(a[2]), "r"(a[3]), "r"(b[0]), "r"(b[1]));
}

// SMEM tile layout (all tc kernels): A_HI[2] @0 (2x16KB), A_LO[2] @32768,
// B_HI[2] @65536 (2x8KB), B_LO[2] @81920. Total 96 KB.
#define VSM_DYN (98304 + 1024)

// ------------------------- one-time pack / init -------------------------
__global__ void pack_kernel(const float* __restrict__ Uw,
                            const float* __restrict__ Wih_f, const float* __restrict__ Whh_f,
                            const float* __restrict__ b_f,
                            const float* __restrict__ Wih_b, const float* __restrict__ Whh_b,
                            const float* __restrict__ b_b,
                            const float* __restrict__ h0, const float* __restrict__ c0) {
    const size_t NTOT = (size_t)2 * H4 * H4;  // 2,097,152
    for (size_t idx = (size_t)blockIdx.x * blockDim.x + threadIdx.x; idx < NTOT;
         idx += (size_t)gridDim.x * blockDim.x) {
        size_t d = idx >> 20;
        size_t r = (idx >> 10) & 1023;
        size_t k = idx & 1023;
        const float* Wih = d ? Wih_b : Wih_f;
        const float* Whh = d ? Whh_b : Whh_f;
        g_Wcat[idx] = (k < H3) ? Wih[r * H3 + k] : Whh[r * H + (k - H3)];

        if (idx < (size_t)H2 * H) {
            size_t j = idx >> 8, kk = idx & 255;
            g_UwS[idx] = Uw[j * H2 + kk] + Uw[j * H2 + H + kk];
        }
        if (idx < 2 * H4) g_bcat[idx] = (idx < H4) ? b_f[idx] : b_b[idx - H4];
        if (idx < 2 * B * H) { g_h[idx] = h0[idx]; g_c[idx] = c0[idx]; }
        // argmax partials: step 0 must resolve to token 0 (x0 = zeros)
        if (idx < (size_t)B * NVT) {
            int tl = (int)(idx % NVT);
            g_pval[idx] = (tl == 0) ? 0.0f : -INFINITY;
            g_pidx[idx] = (tl == 0) ? 0 : 0x7fffffff;
        }
    }
}

// split Fw + enc + Ww into hi/lo bf16 once
__global__ void pack_fw_kernel(const float* __restrict__ Fw,
                               const float* __restrict__ enc,
                               const float* __restrict__ Ww) {
    const size_t NTOT = (size_t)V * H2;
    for (size_t i = (size_t)blockIdx.x * blockDim.x + threadIdx.x; i < NTOT;
         i += (size_t)gridDim.x * blockDim.x) {
        float v = Fw[i];
        __nv_bfloat16 hi = __float2bfloat16(v);
        g_Fw_hi[i] = hi;
        g_Fw_lo[i] = __float2bfloat16(v - __bfloat162float(hi));
        if (i < (size_t)MS * H2) {
            float e = enc[i];
            __nv_bfloat16 ehi = __float2bfloat16(e);
            g_enc_hi[i] = ehi;
            g_enc_lo[i] = __float2bfloat16(e - __bfloat162float(ehi));
        }
        if (i < (size_t)H2 * H2) {
            float w = Ww[i];
            __nv_bfloat16 whi = __float2bfloat16(w);
            g_Ww_hi[i] = whi;
            g_Ww_lo[i] = __float2bfloat16(w - __bfloat162float(whi));
        }
    }
}

// ------------------------- enc_proj on tensor cores (bf16x3, one-time) --------------
// grid (MS/128=64, H2/64=8), 256 thr. encp[m][n] = enc[m][:] . Ww[n][:] + Wb[n]
__global__ void __launch_bounds__(256, 2) enc_tc(const float* __restrict__ Wb,
                                                 float* __restrict__ encp) {
    extern __shared__ char dsm[];
    uint32_t sb0 = smem_u32(dsm);
    uint32_t tb = (sb0 + 1023) & ~1023u;

    const int tid = threadIdx.x;
    const int wid = tid >> 5, lane = tid & 31;
    const int m0 = blockIdx.x * 128;
    const int n0 = blockIdx.y * 64;
    const int wm = wid * 16;

    const int a_row = wm + (lane & 7) + ((lane >> 3) & 1) * 8;
    const int a_kb  = (lane >> 4) * 16;
    const int b_rowi = (lane & 7) + (lane >> 4) * 8;
    const int b_kb  = ((lane >> 3) & 1) * 16;

    float acc[8][4];
    #pragma unroll
    for (int i = 0; i < 8; i++)
        #pragma unroll
        for (int j = 0; j < 4; j++) acc[i][j] = 0.0f;

    #define EISSUE(c)                                                                    \
        do {                                                                             \
            int _buf = (c) & 1;                                                          \
            uint32_t AHI = tb + _buf * 16384u, ALO = tb + 32768u + _buf * 16384u;        \
            uint32_t BHI = tb + 65536u + _buf * 8192u, BLO = tb + 81920u + _buf * 8192u; \
            _Pragma("unroll")                                                            \
            for (int i = 0; i < 4; i++) {                                                \
                int idx = tid + 256 * i;                                                 \
                int r = idx >> 3, q = idx & 7;                                           \
                size_t g = (size_t)(m0 + r) * H2 + (c) * 64 + q * 8;                     \
                uint32_t so = SWZ((uint32_t)(r * 128 + q * 16));                         \
                CP16(AHI + so, (const char*)(g_enc_hi + g));                             \
                CP16(ALO + so, (const char*)(g_enc_lo + g));                             \
            }                                                                            \
            _Pragma("unroll")                                                            \
            for (int i = 0; i < 2; i++) {                                                \
                int idx = tid + 256 * i;                                                 \
                int r = idx >> 3, q = idx & 7;                                           \
                size_t g = (size_t)(n0 + r) * H2 + (c) * 64 + q * 8;                     \
                uint32_t so = SWZ((uint32_t)(r * 128 + q * 16));                         \
                CP16(BHI + so, (const char*)(g_Ww_hi + g));                              \
                CP16(BLO + so, (const char*)(g_Ww_lo + g));                              \
            }                                                                            \
            CP_COMMIT();                                                                 \
        } while (0)

    EISSUE(0);
    EISSUE(1);

    for (int c = 0; c < 8; c++) {
        const int buf = c & 1;
        if (c < 7) { CP_WAIT(1); } else { CP_WAIT(0); }
        __syncthreads();

        const uint32_t AHI = tb + buf * 16384u, ALO = tb + 32768u + buf * 16384u;
        const uint32_t BHI = tb + 65536u + buf * 8192u, BLO = tb + 81920u + buf * 8192u;

        #pragma unroll
        for (int ks = 0; ks < 4; ks++) {
            uint32_t ah[4], al[4];
            uint32_t aoff = SWZ((uint32_t)(a_row * 128 + ks * 32 + a_kb));
            ldsm4(ah, AHI + aoff);
            ldsm4(al, ALO + aoff);
            #pragma unroll
            for (int p = 0; p < 4; p++) {
                uint32_t bh[4], bl[4];
                uint32_t boff = SWZ((uint32_t)((b_rowi + p * 16) * 128 + ks * 32 + b_kb));
                ldsm4(bh, BHI + boff);
                ldsm4(bl, BLO + boff);
                mma16816(acc[2 * p],     ah, bh);
                mma16816(acc[2 * p],     al, bh);
                mma16816(acc[2 * p],     ah, bl);
                mma16816(acc[2 * p + 1], ah, bh + 2);
                mma16816(acc[2 * p + 1], al, bh + 2);
                mma16816(acc[2 * p + 1], ah, bl + 2);
            }
        }
        __syncthreads();
        if (c < 6) EISSUE(c + 2);
    }
    #undef EISSUE

    // epilogue: m-major direct stores with Wb bias (c-frag: rows m, cols n)
    const int row0 = m0 + wm + (lane >> 2);
    const int nb = 2 * (lane & 3);
    #pragma unroll
    for (int nt = 0; nt < 8; nt++) {
        int n = n0 + nt * 8 + nb;
        float2 b2 = *reinterpret_cast<const float2*>(&Wb[n]);
        float2 r0, r1;
        r0.x = acc[nt][0] + b2.x; r0.y = acc[nt][1] + b2.y;
        r1.x = acc[nt][2] + b2.x; r1.y = acc[nt][3] + b2.y;
        *reinterpret_cast<float2*>(&encp[(size_t)row0 * H2 + n]) = r0;
        *reinterpret_cast<float2*>(&encp[(size_t)(row0 + 8) * H2 + n]) = r1;
    }
}

// ------------------------- gates GEMM (fp32, fused gather + fused argmax) -----------
// grid (H4/128=8, KSPLIT_G, 2), 256 thr. k-slices of 128 align with region bounds.
// emb-region blocks (kBegin in [512,768)) first reduce the per-tile argmax partials.
#define GBM 64
#define GBN 128
#define GBK 32
__global__ void __launch_bounds__(256) gates_gemm(const float* __restrict__ embt) {
    const int dz = blockIdx.z;
    const int ks = blockIdx.y;
    const int kBegin = ks * (H4 / KSPLIT_G);
    const float* __restrict__ W = g_Wcat + (size_t)dz * H4 * H4;
    float* __restrict__ C = g_Gp + (size_t)ks * 2 * B * H4 + (size_t)dz * B * H4;

    __shared__ float As[2][GBK][GBM];
    __shared__ float Bs[2][GBK][GBN];
    __shared__ int   xs[B];
    __shared__ float pvs[256];
    __shared__ int   pis[256];

    const int tid = threadIdx.x;
    const int tx = tid & 15, ty = tid >> 4;
    const int nBase = blockIdx.x * GBN;

    const int ar0 = (tid) >> 3,        akq0 = tid & 7;
    const int ar1 = (tid + 256) >> 3,  akq1 = tid & 7;

    const bool need_x = (kBegin >= H2) && (kBegin < H3);
    if (need_x) {
        int bb = tid & 63, part = tid >> 6;
        float bv = -INFINITY; int bi = 0x7fffffff;
        for (int tl = part; tl < NVT; tl += 4) {
            float v = g_pval[bb * NVT + tl];
            int ix = g_pidx[bb * NVT + tl];
            if (v > bv || (v == bv && ix < bi)) { bv = v; bi = ix; }
        }
        pvs[tid] = bv; pis[tid] = bi;
        __syncthreads();
        if (part == 0) {
            #pragma unroll
            for (int p2 = 1; p2 < 4; p2++) {
                float v = pvs[tid + 64 * p2]; int ix = pis[tid + 64 * p2];
                if (v > bv || (v == bv && ix < bi)) { bv = v; bi = ix; }
            }
            xs[bb] = bi;
        }
        __syncthreads();
    }

    const float* aptr0;
    const float* aptr1;
    if (kBegin < H2) {
        aptr0 = g_ctx + (size_t)ar0 * H2 + kBegin;
        aptr1 = g_ctx + (size_t)ar1 * H2 + kBegin;
    } else if (need_x) {
        aptr0 = embt + (size_t)xs[ar0] * H + (kBegin - H2);
        aptr1 = embt + (size_t)xs[ar1] * H + (kBegin - H2);
    } else {
        aptr0 = g_h + ((size_t)dz * B + ar0) * H + (kBegin - H3);
        aptr1 = g_h + ((size_t)dz * B + ar1) * H + (kBegin - H3);
    }

    float acc[4][8];
    #pragma unroll
    for (int i = 0; i < 4; i++)
        #pragma unroll
        for (int j = 0; j < 8; j++) acc[i][j] = 0.0f;

    float4 ra[2], rb[4];

    #define GLOAD_TILE(koff)                                                              \
        do {                                                                              \
            ra[0] = *reinterpret_cast<const float4*>(aptr0 + (koff) + akq0 * 4);          \
            ra[1] = *reinterpret_cast<const float4*>(aptr1 + (koff) + akq1 * 4);          \
            _Pragma("unroll")                                                             \
            for (int i = 0; i < 4; i++) {                                                 \
                int f4 = tid + 256 * i; int r = f4 >> 3, kq = f4 & 7;                     \
                rb[i] = *reinterpret_cast<const float4*>(&W[(size_t)(nBase + r) * H4 + kBegin + (koff) + kq * 4]); \
            }                                                                             \
        } while (0)

    #define STORE_TILE(bi)                                                                \
        do {                                                                              \
            As[bi][akq0 * 4 + 0][ar0] = ra[0].x; As[bi][akq0 * 4 + 1][ar0] = ra[0].y;     \
            As[bi][akq0 * 4 + 2][ar0] = ra[0].z; As[bi][akq0 * 4 + 3][ar0] = ra[0].w;     \
            As[bi][akq1 * 4 + 0][ar1] = ra[1].x; As[bi][akq1 * 4 + 1][ar1] = ra[1].y;     \
            As[bi][akq1 * 4 + 2][ar1] = ra[1].z; As[bi][akq1 * 4 + 3][ar1] = ra[1].w;     \
            _Pragma("unroll")                                                             \
            for (int i = 0; i < 4; i++) {                                                 \
                int f4 = tid + 256 * i; int r = f4 >> 3, kq = f4 & 7;                     \
                Bs[bi][kq * 4 + 0][r] = rb[i].x; Bs[bi][kq * 4 + 1][r] = rb[i].y;         \
                Bs[bi][kq * 4 + 2][r] = rb[i].z; Bs[bi][kq * 4 + 3][r] = rb[i].w;         \
            }                                                                             \
        } while (0)

    #define COMPUTE(bi)                                                                   \
        do {                                                                              \
            _Pragma("unroll")                                                             \
            for (int k = 0; k < GBK; k++) {                                               \
                float4 a4 = *reinterpret_cast<const float4*>(&As[bi][k][ty * 4]);         \
                float4 b0 = *reinterpret_cast<const float4*>(&Bs[bi][k][tx * 8]);         \
                float4 b1 = *reinterpret_cast<const float4*>(&Bs[bi][k][tx * 8 + 4]);     \
                float a[4] = {a4.x, a4.y, a4.z, a4.w};                                    \
                float b[8] = {b0.x, b0.y, b0.z, b0.w, b1.x, b1.y, b1.z, b1.w};            \
                _Pragma("unroll")                                                         \
                for (int i = 0; i < 4; i++)                                               \
                    _Pragma("unroll")                                                     \
                    for (int j = 0; j < 8; j++) acc[i][j] = fmaf(a[i], b[j], acc[i][j]);  \
            }                                                                             \
        } while (0)

    const int nIter = (H4 / KSPLIT_G) / GBK;   // 4
    GLOAD_TILE(0);
    STORE_TILE(0);
    __syncthreads();
    int buf = 0;
    for (int it = 1; it < nIter; it++) {
        GLOAD_TILE(it * GBK);
        COMPUTE(buf);
        STORE_TILE(buf ^ 1);
        __syncthreads();
        buf ^= 1;
    }
    COMPUTE(buf);

    #pragma unroll
    for (int i = 0; i < 4; i++) {
        size_t row = (size_t)(ty * 4 + i);
        #pragma unroll
        for (int j = 0; j < 8; j++) {
            int col = nBase + tx * 8 + j;
            float bj = (ks == 0) ? g_bcat[dz * H4 + col] : 0.0f;
            C[row * H4 + col] = acc[i][j] + bj;
        }
    }
    #undef GLOAD_TILE
    #undef STORE_TILE
    #undef COMPUTE
}

// ------------------------- attention, stage 1: qU = h_f @ UwS.T + Ub ----------------
__global__ void __launch_bounds__(256) attn_qU_kernel(const float* __restrict__ Ub) {
    __shared__ float h_s[H];
    int b = blockIdx.y, tid = threadIdx.x;
    int j0 = blockIdx.x * 64;
    if (tid < H) h_s[tid] = g_h[(size_t)b * H + tid];
    __syncthreads();
    int warp = tid >> 5, lane = tid & 31;
    #pragma unroll
    for (int jj = 0; jj < 8; jj++) {
        int j = j0 + warp * 8 + jj;
        const float* u = g_UwS + (size_t)j * H;
        float s = 0.0f;
        #pragma unroll
        for (int k = lane; k < H; k += 32) s += u[k] * h_s[k];
        s = warpsum(s);
        if (lane == 0) g_qU[(size_t)b * H2 + j] = s + Ub[j];
    }
}

// ------------------------- attention, stage 2: scores -------------------------------
__global__ void __launch_bounds__(256) attn_score_kernel(const float* __restrict__ Vw,
                                                         const float* __restrict__ Vb) {
    __shared__ float qs[H2], vs[H2];
    int b = blockIdx.y, tid = threadIdx.x;
    for (int j = tid; j < H2; j += 256) { qs[j] = g_qU[(size_t)b * H2 + j]; vs[j] = Vw[j]; }
    __syncthreads();
    int warp = tid >> 5, lane = tid & 31;
    float vb = Vb[0];
    #pragma unroll
    for (int i = 0; i < 2; i++) {
        int s = blockIdx.x * 16 + i * 8 + warp;
        const float* ep = g_encp + ((size_t)b * S + s) * H2;
        float acc = 0.0f;
        #pragma unroll 4
        for (int j = lane; j < H2; j += 32) acc += vs[j] * tanhf(qs[j] + ep[j]);
        acc = warpsum(acc);
        if (lane == 0) g_score[(size_t)b * S + s] = acc + vb;
    }
}

// ------------------------- attention, stage 3: softmax + context --------------------
__global__ void __launch_bounds__(128) attn_ctx_kernel(const float* __restrict__ enc) {
    __shared__ float w[S];
    __shared__ float redm[4], reds[4];
    int b = blockIdx.y, tid = threadIdx.x;
    int warp = tid >> 5, lane = tid & 31;

    float sc = g_score[(size_t)b * S + tid];
    float m = warpmax(sc);
    if (lane == 0) redm[warp] = m;
    __syncthreads();
    float mx = fmaxf(fmaxf(redm[0], redm[1]), fmaxf(redm[2], redm[3]));
    float e = expf(sc - mx);
    float su = warpsum(e);
    if (lane == 0) reds[warp] = su;
    __syncthreads();
    float inv = 1.0f / (reds[0] + reds[1] + reds[2] + reds[3]);
    w[tid] = e * inv;
    __syncthreads();

    int d = blockIdx.x * 128 + tid;
    const float* eb = enc + (size_t)b * S * H2 + d;
    float acc = 0.0f;
    #pragma unroll 8
    for (int s = 0; s < S; s++) acc += w[s] * eb[(size_t)s * H2];
    g_ctx[(size_t)b * H2 + d] = acc;
}

// ------------------------- LSTM activation (+ hi/lo split of out) -------------------
__global__ void lstm_act_kernel() {
    int idx = blockIdx.x * blockDim.x + threadIdx.x;
    if (idx >= 2 * B * H) return;
    int d = idx / (B * H);
    int b = (idx / H) % B;
    int k = idx % H;
    size_t base = ((size_t)d * B + b) * H4;
    float gi = 0, gf = 0, gg = 0, go = 0;
    #pragma unroll
    for (int s = 0; s < KSPLIT_G; s++) {
        const float* Gp = g_Gp + (size_t)s * 2 * B * H4 + base;
        gi += Gp[k]; gf += Gp[H + k]; gg += Gp[2 * H + k]; go += Gp[3 * H + k];
    }
    float c_old = g_c[idx];
    float c2 = sigf(gf) * c_old + sigf(gi) * tanhf(gg);
    float h2 = sigf(go) * tanhf(c2);
    g_c[idx] = c2;
    g_h[idx] = h2;
    int o = b * H2 + d * H + k;
    __nv_bfloat16 hi = __float2bfloat16(h2);
    g_out_hi[o] = hi;
    g_out_lo[o] = __float2bfloat16(h2 - __bfloat162float(hi));
}

// ------------------------- vocab GEMM: mma.sync bf16x3 + fused partial argmax -------
__device__ __forceinline__ void vissue_chunk(uint32_t tb, int v0, int c, int buf, int tid) {
    const uint32_t AHI = tb + buf * 16384u, ALO = tb + 32768u + buf * 16384u;
    const uint32_t BHI = tb + 65536u + buf * 8192u, BLO = tb + 81920u + buf * 8192u;
    #pragma unroll
    for (int i = 0; i < 4; i++) {
        int idx = tid + 256 * i;
        int r = idx >> 3, q = idx & 7;
        size_t g = (size_t)(v0 + r) * H2 + c * 64 + q * 8;
        uint32_t so = SWZ((uint32_t)(r * 128 + q * 16));
        CP16(AHI + so, (const char*)(g_Fw_hi + g));
        CP16(ALO + so, (const char*)(g_Fw_lo + g));
    }
    #pragma unroll
    for (int i = 0; i < 2; i++) {
        int idx = tid + 256 * i;
        int r = idx >> 3, q = idx & 7;
        size_t g = (size_t)r * H2 + c * 64 + q * 8;
        uint32_t so = SWZ((uint32_t)(r * 128 + q * 16));
        CP16(BHI + so, (const char*)(g_out_hi + g));
        CP16(BLO + so, (const char*)(g_out_lo + g));
    }
    CP_COMMIT();
}

__global__ void __launch_bounds__(256, 2) vocab_kernel(const float* __restrict__ Fb,
                                                       float* __restrict__ yt) {
    extern __shared__ char dsm[];
    uint32_t sb0 = smem_u32(dsm);
    uint32_t tb = (sb0 + 1023) & ~1023u;
    char* base = dsm + (tb - sb0);

    const int tid = threadIdx.x;
    const int wid = tid >> 5, lane = tid & 31;
    const int v0 = blockIdx.x * 128;
    const int wm = wid * 16;

    const int a_row = wm + (lane & 7) + ((lane >> 3) & 1) * 8;
    const int a_kb  = (lane >> 4) * 16;
    const int b_rowi = (lane & 7) + (lane >> 4) * 8;
    const int b_kb  = ((lane >> 3) & 1) * 16;

    float acc[8][4];
    #pragma unroll
    for (int i = 0; i < 8; i++)
        #pragma unroll
        for (int j = 0; j < 4; j++) acc[i][j] = 0.0f;

    vissue_chunk(tb, v0, 0, 0, tid);
    vissue_chunk(tb, v0, 1, 1, tid);

    for (int c = 0; c < 8; c++) {
        const int buf = c & 1;
        if (c < 7) { CP_WAIT(1); } else { CP_WAIT(0); }
        __syncthreads();

        const uint32_t AHI = tb + buf * 16384u, ALO = tb + 32768u + buf * 16384u;
        const uint32_t BHI = tb + 65536u + buf * 8192u, BLO = tb + 81920u + buf * 8192u;

        #pragma unroll
        for (int ks = 0; ks < 4; ks++) {
            uint32_t ah[4], al[4];
            uint32_t aoff = SWZ((uint32_t)(a_row * 128 + ks * 32 + a_kb));
            ldsm4(ah, AHI + aoff);
            ldsm4(al, ALO + aoff);
            #pragma unroll
            for (int p = 0; p < 4; p++) {
                uint32_t bh[4], bl[4];
                uint32_t boff = SWZ((uint32_t)((b_rowi + p * 16) * 128 + ks * 32 + b_kb));
                ldsm4(bh, BHI + boff);
                ldsm4(bl, BLO + boff);
                mma16816(acc[2 * p],     ah, bh);
                mma16816(acc[2 * p],     al, bh);
                mma16816(acc[2 * p],     ah, bl);
                mma16816(acc[2 * p + 1], ah, bh + 2);
                mma16816(acc[2 * p + 1], al, bh + 2);
                mma16816(acc[2 * p + 1], ah, bl + 2);
            }
        }
        __syncthreads();
        if (c < 6) vissue_chunk(tb, v0, c + 2, buf, tid);
    }

    // epilogue: transpose via smem
    float* tr = (float*)base;   // [64 batch][132]
    {
        const int m0 = wm + (lane >> 2);
        const int nb = 2 * (lane & 3);
        #pragma unroll
        for (int nt = 0; nt < 8; nt++) {
            int n = nt * 8 + nb;
            tr[n * 132 + m0]           = acc[nt][0];
            tr[(n + 1) * 132 + m0]     = acc[nt][1];
            tr[n * 132 + m0 + 8]       = acc[nt][2];
            tr[(n + 1) * 132 + m0 + 8] = acc[nt][3];
        }
    }
    __syncthreads();

    // store with bias + per-(tile,b) argmax partial (first-index tie-break)
    float* pm = tr + 64 * 132;
    int*   pi = (int*)(pm + 256);
    {
        const int bb = tid >> 2;      // batch
        const int t4 = tid & 3;
        float bestv = -INFINITY; int besti = 0x7fffffff;
        #pragma unroll
        for (int i = 0; i < 8; i++) {
            int j = t4 * 8 + i;       // ascending v within thread
            float4 fb4 = *reinterpret_cast<const float4*>(&Fb[v0 + 4 * j]);
            float4 t = *reinterpret_cast<const float4*>(&tr[bb * 132 + 4 * j]);
            float4 r;
            r.x = t.x + fb4.x; r.y = t.y + fb4.y; r.z = t.z + fb4.z; r.w = t.w + fb4.w;
            *reinterpret_cast<float4*>(&yt[(size_t)bb * T * V + v0 + 4 * j]) = r;
            int vbase = v0 + 4 * j;
            if (r.x > bestv) { bestv = r.x; besti = vbase; }
            if (r.y > bestv) { bestv = r.y; besti = vbase + 1; }
            if (r.z > bestv) { bestv = r.z; besti = vbase + 2; }
            if (r.w > bestv) { bestv = r.w; besti = vbase + 3; }
        }
        pm[tid] = bestv; pi[tid] = besti;
    }
    __syncthreads();
    if ((tid & 3) == 0) {
        float bv = pm[tid]; int bi = pi[tid];
        #pragma unroll
        for (int t = 1; t < 4; t++) {
            float v2 = pm[tid + t];
            if (v2 > bv) { bv = v2; bi = pi[tid + t]; }
        }
        int bb = tid >> 2;
        g_pval[bb * NVT + blockIdx.x] = bv;
        g_pidx[bb * NVT + blockIdx.x] = bi;
    }
}

// ------------------------- tail: hT, cT -------------------------
__global__ void tail_kernel(float* __restrict__ out) {
    int idx = blockIdx.x * blockDim.x + threadIdx.x;
    if (idx < 2 * B * H) {
        out[(size_t)B * T * V + idx] = g_h[idx];
        out[(size_t)B * T * V + 2 * B * H + idx] = g_c[idx];
    }
}

// ------------------------- host -------------------------
extern "C" void kernel_launch(void* const* d_in, const int* in_sizes, int n_in,
                              void* d_out, int out_size) {
    const float* enc   = (const float*)d_in[0];
    const float* h0    = (const float*)d_in[1];
    const float* c0    = (const float*)d_in[2];
    const float* Uw    = (const float*)d_in[3];
    const float* Ub    = (const float*)d_in[4];
    const float* Ww    = (const float*)d_in[5];
    const float* Wb    = (const float*)d_in[6];
    const float* Vw    = (const float*)d_in[7];
    const float* Vb    = (const float*)d_in[8];
    const float* Wih_f = (const float*)d_in[9];
    const float* Whh_f = (const float*)d_in[10];
    const float* b_f   = (const float*)d_in[11];
    const float* Wih_b = (const float*)d_in[12];
    const float* Whh_b = (const float*)d_in[13];
    const float* b_b   = (const float*)d_in[14];
    const float* Fw    = (const float*)d_in[15];
    const float* Fb    = (const float*)d_in[16];
    const float* embt  = (const float*)d_in[17];
    (void)in_sizes; (void)n_in;
    float* out = (float*)d_out;

    // one-time host-side setup (no device memory involved)
    static cudaStream_t s2;
    static cudaEvent_t evF, evJ;
    static bool init_done = false;
    if (!init_done) {
        cudaFuncSetAttribute(vocab_kernel, cudaFuncAttributeMaxDynamicSharedMemorySize, VSM_DYN);
        cudaFuncSetAttribute(enc_tc, cudaFuncAttributeMaxDynamicSharedMemorySize, VSM_DYN);
        cudaStreamCreateWithFlags(&s2, cudaStreamNonBlocking);
        cudaEventCreateWithFlags(&evF, cudaEventDisableTiming);
        cudaEventCreateWithFlags(&evJ, cudaEventDisableTiming);
        init_done = true;
    }

    // one-time packing + state init (main stream)
    pack_kernel<<<2048, 1024>>>(Uw, Wih_f, Whh_f, b_f, Wih_b, Whh_b, b_b, h0, c0);
    pack_fw_kernel<<<4096, 256>>>(Fw, enc, Ww);

    // enc_proj = enc @ Ww.T + Wb on tensor cores (bf16x3)
    {
        float* encp;  cudaGetSymbolAddress((void**)&encp, g_encp);
        enc_tc<<<dim3(MS / 128, H2 / 64), 256, VSM_DYN>>>(Wb, encp);
    }

    // attention for step 0 (main stream)
    attn_qU_kernel<<<dim3(8, B), 256>>>(Ub);
    attn_score_kernel<<<dim3(8, B), 256>>>(Vw, Vb);
    attn_ctx_kernel<<<dim3(4, B), 128>>>(enc);

    for (int t = 0; t < T; t++) {
        // main: gates (consumes ctx(t) + argmax partials(t-1)) -> act
        gates_gemm<<<dim3(H4 / GBN, KSPLIT_G, 2), 256>>>(embt);
        lstm_act_kernel<<<(2 * B * H) / 256, 256>>>();

        // fork: s2 runs attention for step t+1 concurrently with vocab(t)
        cudaEventRecord(evF, 0);
        cudaStreamWaitEvent(s2, evF, 0);

        vocab_kernel<<<NVT, 256, VSM_DYN>>>(Fb, out + (size_t)t * V);

        attn_qU_kernel<<<dim3(8, B), 256, 0, s2>>>(Ub);
        attn_score_kernel<<<dim3(8, B), 256, 0, s2>>>(Vw, Vb);
        attn_ctx_kernel<<<dim3(4, B), 128, 0, s2>>>(enc);

        // join
        cudaEventRecord(evJ, s2);
        cudaStreamWaitEvent(0, evJ, 0);
    }

    if (out_size >= B * T * V + 4 * B * H)
        tail_kernel<<<(2 * B * H + 255) / 256, 256>>>(out);
}